// round 14
// baseline (speedup 1.0000x reference)
#include <cuda_runtime.h>
#include <cuda_fp16.h>
#include <stdint.h>

#define BB 2
#define TT 2048
#define CC 1024
#define HH 16
#define DD 64

// ---------------------------------------------------------------------------
// Scratch (allocation-free rule: __device__ globals). Device-code refs only.
// ---------------------------------------------------------------------------
__device__ float g_v[BB * HH * TT * DD];
__device__ float g_e[(size_t)BB * HH * TT * TT];   // fp32: precision-critical
__device__ float g_mh[(size_t)BB * HH * TT * 32];
__device__ uint32_t g_mask[(size_t)BB * HH * TT * (TT / 32)];
// q, k in 2-way f16 decomposition (h + l ~ fp32): [bh][t][d]
__device__ __half g_qh[BB * HH * TT * DD], g_ql[BB * HH * TT * DD];
__device__ __half g_kh[BB * HH * TT * DD], g_kl[BB * HH * TT * DD];
// split-f16 GEMM operands
__device__ __half g_xh[BB * TT * CC], g_xl[BB * TT * CC];
__device__ __half g_wqh[3 * CC * CC], g_wql[3 * CC * CC];
__device__ __half g_woh[CC * CC], g_wol[CC * CC];
__device__ __half g_aoh[BB * TT * CC], g_aol[BB * TT * CC];
// V transposed per (b,h): [bh][d][t], f16 hi/lo
__device__ __half g_vth[(size_t)BB * HH * DD * TT];
__device__ __half g_vtl[(size_t)BB * HH * DD * TT];

// ---------------------------------------------------------------------------
// sm_80-level PTX helpers
// ---------------------------------------------------------------------------
__device__ __forceinline__ uint32_t smem_u32(const void* p) {
    uint32_t a;
    asm("{ .reg .u64 t; cvta.to.shared.u64 t, %1; cvt.u32.u64 %0, t; }"
        : "=r"(a) : "l"(p));
    return a;
}
__device__ __forceinline__ void cp16(uint32_t dst, const void* src) {
    asm volatile("cp.async.cg.shared.global [%0], [%1], 16;"
                 :: "r"(dst), "l"(src) : "memory");
}
#define CP_COMMIT() asm volatile("cp.async.commit_group;" ::: "memory")
#define CP_WAIT(n)  asm volatile("cp.async.wait_group %0;" :: "n"(n) : "memory")

// f16 x f16 -> f32 accumulate MMA
__device__ __forceinline__ void mma16816(float* c, const uint32_t* a,
                                         const uint32_t* b) {
    asm volatile(
        "mma.sync.aligned.m16n8k16.row.col.f32.f16.f16.f32 "
        "{%0,%1,%2,%3},{%4,%5,%6,%7},{%8,%9},{%0,%1,%2,%3};"
        : "+f"(c[0]), "+f"(c[1]), "+f"(c[2]), "+f"(c[3])
        : "r"(a[0]), "r"(a[1]), "r"(a[2]), "r"(a[3]), "r"(b[0]), "r"(b[1]));
}
__device__ __forceinline__ uint32_t pk(__half a, __half b) {
    return (uint32_t)__half_as_ushort(a) |
           ((uint32_t)__half_as_ushort(b) << 16);
}
__device__ __forceinline__ void split2(float v, __half& h, __half& l) {
    h = __float2half_rn(v);
    l = __float2half_rn(v - __half2float(h));
}

// ---------------------------------------------------------------------------
// Threefry-2x32, key = (0, 42)
// ---------------------------------------------------------------------------
__device__ __forceinline__ uint2 threefry_0_42(uint32_t x0, uint32_t x1) {
    const uint32_t ks0 = 0u, ks1 = 42u;
    const uint32_t ks2 = 0x1BD11BDAu ^ ks0 ^ ks1;
    x0 += ks0; x1 += ks1;
#define TF_RND(rot) { x0 += x1; x1 = __funnelshift_l(x1, x1, (rot)); x1 ^= x0; }
    TF_RND(13) TF_RND(15) TF_RND(26) TF_RND(6)
    x0 += ks1; x1 += ks2 + 1u;
    TF_RND(17) TF_RND(29) TF_RND(16) TF_RND(24)
    x0 += ks2; x1 += ks0 + 2u;
    TF_RND(13) TF_RND(15) TF_RND(26) TF_RND(6)
    x0 += ks0; x1 += ks1 + 3u;
    TF_RND(17) TF_RND(29) TF_RND(16) TF_RND(24)
    x0 += ks1; x1 += ks2 + 4u;
    TF_RND(13) TF_RND(15) TF_RND(26) TF_RND(6)
    x0 += ks2; x1 += ks0 + 5u;
#undef TF_RND
    return make_uint2(x0, x1);
}
__device__ __forceinline__ bool regrow_test(uint32_t idx) {
    uint2 rb = threefry_0_42(0u, idx);
    return ((rb.x ^ rb.y) >> 9) <= 419430u;
}

// ---------------------------------------------------------------------------
// fp32 -> f16 hi/lo split: x -> g_xh/g_xl
// ---------------------------------------------------------------------------
__global__ void __launch_bounds__(256)
conv_rows(const float* __restrict__ X, int n4) {
    int i = blockIdx.x * 256 + threadIdx.x;
    if (i >= n4) return;
    float4 v = ((const float4*)X)[i];
    float vv[4] = {v.x, v.y, v.z, v.w};
    __half h[4], l[4];
#pragma unroll
    for (int j = 0; j < 4; j++) split2(vv[j], h[j], l[j]);
    ((uint32_t*)g_xh)[i * 2]     = pk(h[0], h[1]);
    ((uint32_t*)g_xh)[i * 2 + 1] = pk(h[2], h[3]);
    ((uint32_t*)g_xl)[i * 2]     = pk(l[0], l[1]);
    ((uint32_t*)g_xl)[i * 2 + 1] = pk(l[2], l[3]);
}

// W [K][N] fp32 -> W^T [N][K] f16 hi/lo.  sel 0: g_wqh/g_wql, 1: g_woh/g_wol
__global__ void __launch_bounds__(256)
conv_tr(const float* __restrict__ W, int K, int N, int sel) {
    __shared__ float sm[32][33];
    __half* Th = (sel == 0) ? g_wqh : g_woh;
    __half* Tl = (sel == 0) ? g_wql : g_wol;
    const int n0 = blockIdx.x * 32, k0 = blockIdx.y * 32;
    const int tx = threadIdx.x, ty = threadIdx.y;
#pragma unroll
    for (int i = 0; i < 4; i++)
        sm[ty + i * 8][tx] = W[(size_t)(k0 + ty + i * 8) * N + n0 + tx];
    __syncthreads();
#pragma unroll
    for (int i = 0; i < 4; i++) {
        float v = sm[tx][ty + i * 8];
        __half h, l;
        split2(v, h, l);
        size_t o = (size_t)(n0 + ty + i * 8) * K + k0 + tx;
        Th[o] = h; Tl[o] = l;
    }
}

// g_v [bh][t][d] fp32 -> g_vth/g_vtl [bh][d][t] f16 hi/lo
__global__ void __launch_bounds__(256)
vt_split() {
    __shared__ float sm[32][33];
    const int bh = blockIdx.z;
    const int d0 = blockIdx.x * 32;
    const int t0 = blockIdx.y * 32;
    const int tx = threadIdx.x, ty = threadIdx.y;
    const float* src = g_v + (size_t)bh * TT * DD;
#pragma unroll
    for (int i = 0; i < 4; i++)
        sm[ty + i * 8][tx] = src[(size_t)(t0 + ty + i * 8) * DD + d0 + tx];
    __syncthreads();
#pragma unroll
    for (int i = 0; i < 4; i++) {
        float v = sm[tx][ty + i * 8];
        __half h, l;
        split2(v, h, l);
        size_t o = ((size_t)bh * DD + d0 + ty + i * 8) * TT + t0 + tx;
        g_vth[o] = h; g_vtl[o] = l;
    }
}

// ---------------------------------------------------------------------------
// Split-f16 HMMA GEMM: C = A @ Bt^T + bias.
//   sel 0: A=g_xh/g_xl, Bt=g_wqh/g_wql; scatter q,k as 2-way f16, v fp32.
//          ALSO generates the regrow bitmask as ALU filler work interleaved
//          with the tensor-pipe MMAs (155M ALU instrs ride the idle issue
//          slots under the HMMA stream).
//   sel 1: A=g_aoh/g_aol, Bt=g_woh/g_wol; row-major store to Cout.
// ---------------------------------------------------------------------------
#define GOPE   (128 * 40)
#define GSTAGE (4 * GOPE)
#define GEMM_SMEM (2 * GSTAGE * 2)

// triangular mask words: 32 bh x sum_{tb=0..63} 32 rows * (tb+1) words
#define MASK_WORDS_PER_BH 66560u
#define MASK_TOTAL (32u * MASK_WORDS_PER_BH)      // 2129920
#define MASK_PER_WARP 347u                        // ceil(TOTAL / 6144 warps)
#define MASK_PER_CHUNK 11                         // 32 chunks * 11 >= 347

__global__ void __launch_bounds__(256)
hmma_gemm(const float* __restrict__ bias, float* __restrict__ Cout, int sel) {
    extern __shared__ __half gsm[];
    const __half* Ah = (sel == 0) ? g_xh : g_aoh;
    const __half* Al = (sel == 0) ? g_xl : g_aol;
    const __half* Bh = (sel == 0) ? g_wqh : g_woh;
    const __half* Bl = (sel == 0) ? g_wql : g_wol;
    const int Kdim = CC;
    const int Ncols = (sel == 0) ? 3 * CC : CC;

    const int tid = threadIdx.x;
    const int lane = tid & 31, wid = tid >> 5;
    const int wm = wid & 3, wn = wid >> 2;
    const int n0 = blockIdx.x * 128, m0 = blockIdx.y * 128;
    const int g = lane >> 2, j2 = (lane & 3) * 2;

    // ---- mask filler state (sel==0 only): decode flat triangular index ----
    uint32_t mk_rem = 0;
    int mk_bh = 0, mk_tb = 0, mk_wpr = 1, mk_row = 0, mk_w = 0;
    if (sel == 0) {
        uint32_t warpG =
            (uint32_t)((blockIdx.y * gridDim.x + blockIdx.x) * 8 + wid);
        uint32_t f0 = warpG * MASK_PER_WARP;
        if (f0 < MASK_TOTAL) {
            uint32_t left = MASK_TOTAL - f0;
            mk_rem = left < MASK_PER_WARP ? left : MASK_PER_WARP;
            mk_bh = (int)(f0 / MASK_WORDS_PER_BH);
            int rem = (int)(f0 - (uint32_t)mk_bh * MASK_WORDS_PER_BH);
            float s = sqrtf((float)rem * 0.25f + 1.0f);
            int tb = (int)((s - 1.0f) * 0.5f);
            if (16 * (tb + 1) * (tb + 2) <= rem) tb++;
            if (16 * tb * (tb + 1) > rem) tb--;
            int inner = rem - 16 * tb * (tb + 1);
            int wpr = tb + 1;
            int row = (int)(__fdividef((float)inner, (float)wpr));
            if (row * wpr > inner) row--;
            if (inner - row * wpr >= wpr) row++;
            mk_tb = tb; mk_wpr = wpr; mk_row = row;
            mk_w = inner - row * wpr;
        }
    }

    float acc[2][8][4];
#pragma unroll
    for (int mi = 0; mi < 2; mi++)
#pragma unroll
        for (int ni = 0; ni < 8; ni++)
#pragma unroll
            for (int r = 0; r < 4; r++) acc[mi][ni][r] = 0.f;

    const int nch = Kdim / 32;

#define ISSUE_LOADS(IT, STAGE) do {                                          \
        const int _k0 = (IT) * 32;                                          \
        __half* _sb = gsm + (STAGE) * GSTAGE;                               \
        _Pragma("unroll")                                                    \
        for (int _r = 0; _r < 2; _r++) {                                     \
            int _c = _r * 256 + tid;                                         \
            int _row = _c >> 2, _off = (_c & 3) * 8;                         \
            uint32_t _so = smem_u32(_sb + _row * 40 + _off);                 \
            size_t _ga = (size_t)(m0 + _row) * Kdim + _k0 + _off;            \
            size_t _gb = (size_t)(n0 + _row) * Kdim + _k0 + _off;            \
            cp16(_so,                 Ah + _ga);                             \
            cp16(_so + 2 * GOPE,      Al + _ga);                             \
            cp16(_so + 4 * GOPE,      Bh + _gb);                             \
            cp16(_so + 6 * GOPE,      Bl + _gb);                             \
        }                                                                    \
    } while (0)

    ISSUE_LOADS(0, 0);
    CP_COMMIT();

    for (int it = 0; it < nch; it++) {
        if (it + 1 < nch) {
            ISSUE_LOADS(it + 1, (it + 1) & 1);
            CP_COMMIT();
            CP_WAIT(1);
        } else {
            CP_WAIT(0);
        }
        __syncthreads();

        const __half* sAh = gsm + (it & 1) * GSTAGE;
        const __half* sAl = sAh + GOPE;
        const __half* sBh = sAh + 2 * GOPE;
        const __half* sBl = sAh + 3 * GOPE;

#pragma unroll
        for (int ks = 0; ks < 2; ks++) {
            const int k0 = ks * 16;
            uint32_t ah[2][4], al[2][4], bh[8][2], bl[8][2];
#pragma unroll
            for (int mi = 0; mi < 2; mi++) {
                int row = wm * 32 + mi * 16;
                ah[mi][0] = *(const uint32_t*)&sAh[(row + g) * 40 + k0 + j2];
                ah[mi][1] = *(const uint32_t*)&sAh[(row + 8 + g) * 40 + k0 + j2];
                ah[mi][2] = *(const uint32_t*)&sAh[(row + g) * 40 + k0 + j2 + 8];
                ah[mi][3] = *(const uint32_t*)&sAh[(row + 8 + g) * 40 + k0 + j2 + 8];
                al[mi][0] = *(const uint32_t*)&sAl[(row + g) * 40 + k0 + j2];
                al[mi][1] = *(const uint32_t*)&sAl[(row + 8 + g) * 40 + k0 + j2];
                al[mi][2] = *(const uint32_t*)&sAl[(row + g) * 40 + k0 + j2 + 8];
                al[mi][3] = *(const uint32_t*)&sAl[(row + 8 + g) * 40 + k0 + j2 + 8];
            }
#pragma unroll
            for (int ni = 0; ni < 8; ni++) {
                int n = wn * 64 + ni * 8 + g;
                bh[ni][0] = *(const uint32_t*)&sBh[n * 40 + k0 + j2];
                bh[ni][1] = *(const uint32_t*)&sBh[n * 40 + k0 + j2 + 8];
                bl[ni][0] = *(const uint32_t*)&sBl[n * 40 + k0 + j2];
                bl[ni][1] = *(const uint32_t*)&sBl[n * 40 + k0 + j2 + 8];
            }
#pragma unroll
            for (int mi = 0; mi < 2; mi++)
#pragma unroll
                for (int ni = 0; ni < 8; ni++) {
                    mma16816(acc[mi][ni], ah[mi], bh[ni]);
                    mma16816(acc[mi][ni], ah[mi], bl[ni]);
                    mma16816(acc[mi][ni], al[mi], bh[ni]);
                }
        }

        // ---- mask filler: ~11 ballot-words per chunk ride the MMA latency --
        if (sel == 0 && mk_rem) {
            int todo = mk_rem < (uint32_t)MASK_PER_CHUNK ? (int)mk_rem
                                                         : MASK_PER_CHUNK;
            for (int z = 0; z < todo; z++) {
                int t = mk_tb * 32 + mk_row;
                uint32_t idx = ((uint32_t)(mk_bh * TT + t)) * (uint32_t)TT +
                               (uint32_t)(mk_w * 32) + (uint32_t)lane;
                uint32_t wordv =
                    __ballot_sync(0xffffffffu, regrow_test(idx));
                if (lane == 0)
                    g_mask[((size_t)(mk_bh * TT + t)) * (TT / 32) + mk_w] =
                        wordv;
                if (++mk_w == mk_wpr) {
                    mk_w = 0;
                    if (++mk_row == 32) {
                        mk_row = 0; mk_tb++; mk_wpr++;
                        if (mk_tb == 64) { mk_tb = 0; mk_wpr = 1; mk_bh++; }
                    }
                }
            }
            mk_rem -= (uint32_t)todo;
        }
        __syncthreads();
    }

#pragma unroll
    for (int mi = 0; mi < 2; mi++) {
#pragma unroll
        for (int ni = 0; ni < 8; ni++) {
            int m_r = m0 + wm * 32 + mi * 16 + g;
            int n_c = n0 + wn * 64 + ni * 8 + j2;
            float b0 = bias[n_c], b1 = bias[n_c + 1];
            float v00 = acc[mi][ni][0] + b0, v01 = acc[mi][ni][1] + b1;
            float v10 = acc[mi][ni][2] + b0, v11 = acc[mi][ni][3] + b1;
            if (sel == 1) {
                *(float2*)&Cout[(size_t)m_r * Ncols + n_c] = make_float2(v00, v01);
                *(float2*)&Cout[(size_t)(m_r + 8) * Ncols + n_c] = make_float2(v10, v11);
            } else {
                int part = n_c >> 10, rem = n_c & 1023;
                int hh = rem >> 6, dd = rem & 63;
                int b = m_r >> 11, t = m_r & 2047;
                int b2 = (m_r + 8) >> 11, t2 = (m_r + 8) & 2047;
                size_t o1 = (((size_t)b * HH + hh) * TT + t) * DD + dd;
                size_t o2 = (((size_t)b2 * HH + hh) * TT + t2) * DD + dd;
                if (part == 2) {
                    *(float2*)&g_v[o1] = make_float2(v00, v01);
                    *(float2*)&g_v[o2] = make_float2(v10, v11);
                } else {
                    __half* AH = (part == 0) ? g_qh : g_kh;
                    __half* AL = (part == 0) ? g_ql : g_kl;
                    __half h0, l0, h1, l1;
                    split2(v00, h0, l0);
                    split2(v01, h1, l1);
                    ((uint32_t*)AH)[o1 >> 1] = pk(h0, h1);
                    ((uint32_t*)AL)[o1 >> 1] = pk(l0, l1);
                    split2(v10, h0, l0);
                    split2(v11, h1, l1);
                    ((uint32_t*)AH)[o2 >> 1] = pk(h0, h1);
                    ((uint32_t*)AL)[o2 >> 1] = pk(l0, l1);
                }
            }
        }
    }
#undef ISSUE_LOADS
}

// ---------------------------------------------------------------------------
// Attention, f16 2-way splits (3-term MMAs), occupancy 2, e cached fp32.
// Pass 1: QK HMMA + fragment softmax (quad shuffles), e -> g_e (fp32).
// Pass 2: sparsify + AV HMMA.
// smem layout (91136 B, 2 blocks/SM):
//   stgA [0,18432) | stgB [18432,36864)   (k / vt tiles, both passes)
//   pass1: q2 [36864,73728)
//   pass2: mh [36864,53248) | a_h [53248,71680) | a_l [71680,90112) |
//          mfin [90112,90624) | lfin [90624,91136)
// ---------------------------------------------------------------------------
#define ATTN_SMEM 91136

__global__ void __launch_bounds__(256, 2)
attn_kernel() {
    extern __shared__ char asmem[];
    __half* stgA = (__half*)asmem;
    __half* stgB = (__half*)(asmem + 18432);
    __half* q_sm = (__half*)(asmem + 36864);
    float (*mh_s)[32] = (float(*)[32])(asmem + 36864);
    __half* a_smh = (__half*)(asmem + 53248);
    __half* a_sml = (__half*)(asmem + 71680);
    float* mfin = (float*)(asmem + 90112);
    float* lfin = (float*)(asmem + 90624);

    const int NQB = TT / 128;
    const int bh = blockIdx.z * HH + blockIdx.y;
    const int tid = threadIdx.x;
    const int ty = tid >> 4;
    const int tx = tid & 15;
    const int lane = tid & 31, wid = tid >> 5;
    const int wm = wid & 3, wn = wid >> 2;
    const int g = lane >> 2, qd = lane & 3, j2 = qd * 2;

    const uint32_t* qh32 = (const uint32_t*)q_sm;
    const uint32_t* ql32 = qh32 + 4608;

    for (int half = 0; half < 2; half++) {
        const int qb = half == 0 ? (NQB - 1 - (int)blockIdx.x) : (int)blockIdx.x;
        const int t0 = qb * 128;
        const int ntiles = 2 * qb + 2;

        // ---- stage q2 via cp.async (2048 chunks, 8/thread) ----
#pragma unroll
        for (int rep = 0; rep < 8; rep++) {
            int c = rep * 256 + tid;
            int arr = c >> 10, cc = c & 1023, row = cc >> 3, j = cc & 7;
            const __half* src = (arr == 0 ? g_qh : g_ql) +
                ((size_t)bh * TT + t0 + row) * DD + j * 8;
            cp16(smem_u32(q_sm + arr * 9216 + row * 72 + j * 8), src);
        }
        CP_COMMIT();
        // ---- stage k2 tile 0 (1024 chunks, 4/thread) ----
#pragma unroll
        for (int rep = 0; rep < 4; rep++) {
            int c = rep * 256 + tid;
            int arr = c >> 9, cc = c & 511, row = cc >> 3, j = cc & 7;
            const __half* src = (arr == 0 ? g_kh : g_kl) +
                ((size_t)bh * TT + row) * DD + j * 8;
            cp16(smem_u32(stgA + arr * 4608 + row * 72 + j * 8), src);
        }
        CP_COMMIT();
        CP_WAIT(1);               // q done (k0 may still be in flight)
        __syncthreads();

        // ---- Q fragments in registers ----
        uint32_t qfh[4][4], qfl[4][4];
#pragma unroll
        for (int ks = 0; ks < 4; ks++) {
            int b0 = (16 * wid + g) * 36 + ks * 8 + qd;
            int b1 = b0 + 8 * 36;
            qfh[ks][0] = qh32[b0]; qfh[ks][1] = qh32[b1];
            qfh[ks][2] = qh32[b0 + 4]; qfh[ks][3] = qh32[b1 + 4];
            qfl[ks][0] = ql32[b0]; qfl[ks][1] = ql32[b1];
            qfl[ks][2] = ql32[b0 + 4]; qfl[ks][3] = ql32[b1 + 4];
        }

        const int r0 = 16 * wid + g, r1 = r0 + 8;
        const int tg0 = t0 + r0, tg1 = t0 + r1;
        float m0 = -1e30f, m1 = -1e30f, l0 = 0.f, l1 = 0.f;
        float* erow0 = g_e + ((size_t)(bh * TT + tg0)) * TT;
        float* erow1 = g_e + ((size_t)(bh * TT + tg1)) * TT;

        // ---------------- Pass 1 ----------------
        for (int it = 0; it < ntiles; it++) {
            const int s0 = it * 64;
            CP_WAIT(0);
            __syncthreads();
            if (it + 1 < ntiles) {
                __half* stn = ((it + 1) & 1) ? stgB : stgA;
#pragma unroll
                for (int rep = 0; rep < 4; rep++) {
                    int c = rep * 256 + tid;
                    int arr = c >> 9, cc = c & 511, row = cc >> 3, j = cc & 7;
                    const __half* src = (arr == 0 ? g_kh : g_kl) +
                        ((size_t)bh * TT + s0 + 64 + row) * DD + j * 8;
                    cp16(smem_u32(stn + arr * 4608 + row * 72 + j * 8), src);
                }
                CP_COMMIT();
            }

            const uint32_t* kh32s =
                (const uint32_t*)((it & 1) ? stgB : stgA);
            const uint32_t* kl32s = kh32s + 2304;

            float acc[8][4];
#pragma unroll
            for (int ni = 0; ni < 8; ni++)
#pragma unroll
                for (int r = 0; r < 4; r++) acc[ni][r] = 0.f;

#pragma unroll
            for (int ks = 0; ks < 4; ks++) {
#pragma unroll
                for (int ni = 0; ni < 8; ni++) {
                    int bb = (ni * 8 + g) * 36 + ks * 8 + qd;
                    uint32_t b_h[2] = {kh32s[bb], kh32s[bb + 4]};
                    uint32_t b_l[2] = {kl32s[bb], kl32s[bb + 4]};
                    mma16816(acc[ni], qfh[ks], b_h);
                    mma16816(acc[ni], qfl[ks], b_h);
                    mma16816(acc[ni], qfh[ks], b_l);
                }
            }

            // ---- fragment softmax (quad-shuffle reductions) ----
            float tm0 = -1e30f, tm1 = -1e30f;
#pragma unroll
            for (int ni = 0; ni < 8; ni++) {
                int s = s0 + ni * 8 + j2;
                acc[ni][0] = (s     <= tg0) ? acc[ni][0] * 0.125f : -1e30f;
                acc[ni][1] = (s + 1 <= tg0) ? acc[ni][1] * 0.125f : -1e30f;
                acc[ni][2] = (s     <= tg1) ? acc[ni][2] * 0.125f : -1e30f;
                acc[ni][3] = (s + 1 <= tg1) ? acc[ni][3] * 0.125f : -1e30f;
                tm0 = fmaxf(tm0, fmaxf(acc[ni][0], acc[ni][1]));
                tm1 = fmaxf(tm1, fmaxf(acc[ni][2], acc[ni][3]));
            }
            tm0 = fmaxf(tm0, __shfl_xor_sync(0xffffffffu, tm0, 1));
            tm0 = fmaxf(tm0, __shfl_xor_sync(0xffffffffu, tm0, 2));
            tm1 = fmaxf(tm1, __shfl_xor_sync(0xffffffffu, tm1, 1));
            tm1 = fmaxf(tm1, __shfl_xor_sync(0xffffffffu, tm1, 2));
            float mn0 = fmaxf(m0, tm0), mn1 = fmaxf(m1, tm1);
            float ls0 = 0.f, ls1 = 0.f;
#pragma unroll
            for (int ni = 0; ni < 8; ni++) {
                acc[ni][0] = __expf(acc[ni][0] - mn0);
                acc[ni][1] = __expf(acc[ni][1] - mn0);
                acc[ni][2] = __expf(acc[ni][2] - mn1);
                acc[ni][3] = __expf(acc[ni][3] - mn1);
                ls0 += acc[ni][0] + acc[ni][1];
                ls1 += acc[ni][2] + acc[ni][3];
            }
            ls0 += __shfl_xor_sync(0xffffffffu, ls0, 1);
            ls0 += __shfl_xor_sync(0xffffffffu, ls0, 2);
            ls1 += __shfl_xor_sync(0xffffffffu, ls1, 1);
            ls1 += __shfl_xor_sync(0xffffffffu, ls1, 2);
            l0 = l0 * __expf(m0 - mn0) + ls0; m0 = mn0;
            l1 = l1 * __expf(m1 - mn1) + ls1; m1 = mn1;

            // store e as fp32 pairs (precision-critical)
#pragma unroll
            for (int ni = 0; ni < 8; ni++) {
                *(float2*)&erow0[s0 + ni * 8 + j2] =
                    make_float2(acc[ni][0], acc[ni][1]);
                *(float2*)&erow1[s0 + ni * 8 + j2] =
                    make_float2(acc[ni][2], acc[ni][3]);
            }
            if (qd == 0) {
                g_mh[((size_t)(bh * TT + tg0)) * 32 + it] = mn0;
                g_mh[((size_t)(bh * TT + tg1)) * 32 + it] = mn1;
            }
        }

        __syncthreads();
        if (qd == 0) {
            mfin[r0] = m0; lfin[r0] = 1.0f / l0;
            mfin[r1] = m1; lfin[r1] = 1.0f / l1;
        }
        // issue vt tile 0
#pragma unroll
        for (int rep = 0; rep < 4; rep++) {
            int c = rep * 256 + tid;
            int arr = c >> 9, cc = c & 511, d = cc >> 3, j = cc & 7;
            const __half* src =
                (arr ? g_vtl : g_vth) + ((size_t)bh * DD + d) * TT + j * 8;
            cp16(smem_u32(stgA + arr * 4608 + d * 72 + j * 8), src);
        }
        CP_COMMIT();
        __syncthreads();

        // factors c_it = exp(mh - m_fin) / l into mh_s
#pragma unroll
        for (int i = 0; i < 8; i++) {
            int row = ty * 8 + i;
            float mf = mfin[row], il = lfin[row];
            for (int it2 = tx; it2 < ntiles; it2 += 16)
                mh_s[row][it2] =
                    __expf(g_mh[((size_t)(bh * TT + t0 + row)) * 32 + it2] - mf) * il;
        }

        // ---------------- Pass 2 ----------------
        float acc2[2][4][4];
#pragma unroll
        for (int mi = 0; mi < 2; mi++)
#pragma unroll
            for (int ni = 0; ni < 4; ni++)
#pragma unroll
                for (int r = 0; r < 4; r++) acc2[mi][ni][r] = 0.f;

        for (int it = 0; it < ntiles; it++) {
            const int s0 = it * 64;
            CP_WAIT(0);
            __syncthreads();
            if (it + 1 < ntiles) {
                __half* stn = ((it + 1) & 1) ? stgB : stgA;
#pragma unroll
                for (int rep = 0; rep < 4; rep++) {
                    int c = rep * 256 + tid;
                    int arr = c >> 9, cc = c & 511, d = cc >> 3, j = cc & 7;
                    const __half* src = (arr ? g_vtl : g_vth) +
                        ((size_t)bh * DD + d) * TT + s0 + 64 + j * 8;
                    cp16(smem_u32(stn + arr * 4608 + d * 72 + j * 8), src);
                }
                CP_COMMIT();
            }

            // sparsify + split a into f16 hi/lo
#pragma unroll
            for (int i = 0; i < 8; i++) {
                const int row = ty * 8 + i;
                const int t = t0 + row;
                const float fac = mh_s[row][it];
                const float* erow = g_e + ((size_t)(bh * TT + t)) * TT;
                float4 ev = *(const float4*)&erow[s0 + tx * 4];
                uint32_t word = g_mask[((size_t)(bh * TT + t)) * (TT / 32) +
                                       (s0 >> 5) + (tx >> 3)];
                int bp = (tx & 7) * 4;
                float a0 = ev.x * fac, a1 = ev.y * fac,
                      a2 = ev.z * fac, a3 = ev.w * fac;
                a0 = (a0 > 0.01f || ((word >> (bp + 0)) & 1u)) ? a0 : 0.f;
                a1 = (a1 > 0.01f || ((word >> (bp + 1)) & 1u)) ? a1 : 0.f;
                a2 = (a2 > 0.01f || ((word >> (bp + 2)) & 1u)) ? a2 : 0.f;
                a3 = (a3 > 0.01f || ((word >> (bp + 3)) & 1u)) ? a3 : 0.f;
                __half h0, lo0, h1, lo1, h2, lo2, h3, lo3;
                split2(a0, h0, lo0); split2(a1, h1, lo1);
                split2(a2, h2, lo2); split2(a3, h3, lo3);
                uint32_t idx = row * 36 + tx * 2;
                ((uint32_t*)a_smh)[idx]     = pk(h0, h1);
                ((uint32_t*)a_smh)[idx + 1] = pk(h2, h3);
                ((uint32_t*)a_sml)[idx]     = pk(lo0, lo1);
                ((uint32_t*)a_sml)[idx + 1] = pk(lo2, lo3);
            }
            __syncthreads();

            const uint32_t* ah32 = (const uint32_t*)a_smh;
            const uint32_t* al32 = (const uint32_t*)a_sml;
            const uint32_t* vh32 =
                (const uint32_t*)((it & 1) ? stgB : stgA);
            const uint32_t* vl32 = vh32 + 2304;
#pragma unroll
            for (int ks = 0; ks < 4; ks++) {
                uint32_t ah[2][4], al[2][4], bh[4][2], bl[4][2];
#pragma unroll
                for (int mi = 0; mi < 2; mi++) {
                    int base = (wm * 32 + mi * 16 + g) * 36 + ks * 8 + qd;
                    ah[mi][0] = ah32[base];
                    ah[mi][1] = ah32[base + 8 * 36];
                    ah[mi][2] = ah32[base + 4];
                    ah[mi][3] = ah32[base + 8 * 36 + 4];
                    al[mi][0] = al32[base];
                    al[mi][1] = al32[base + 8 * 36];
                    al[mi][2] = al32[base + 4];
                    al[mi][3] = al32[base + 8 * 36 + 4];
                }
#pragma unroll
                for (int ni = 0; ni < 4; ni++) {
                    int base = (wn * 32 + ni * 8 + g) * 36 + ks * 8 + qd;
                    bh[ni][0] = vh32[base];
                    bh[ni][1] = vh32[base + 4];
                    bl[ni][0] = vl32[base];
                    bl[ni][1] = vl32[base + 4];
                }
#pragma unroll
                for (int mi = 0; mi < 2; mi++)
#pragma unroll
                    for (int ni = 0; ni < 4; ni++) {
                        mma16816(acc2[mi][ni], ah[mi], bh[ni]);
                        mma16816(acc2[mi][ni], ah[mi], bl[ni]);
                        mma16816(acc2[mi][ni], al[mi], bh[ni]);
                    }
            }
        }

        // epilogue: split output, write g_aoh/g_aol directly
        const int b = blockIdx.z, h = blockIdx.y;
#pragma unroll
        for (int mi = 0; mi < 2; mi++) {
#pragma unroll
            for (int ni = 0; ni < 4; ni++) {
                int mrow = wm * 32 + mi * 16 + g;
                int n = wn * 32 + ni * 8 + j2;
#pragma unroll
                for (int rr = 0; rr < 2; rr++) {
                    int t = t0 + mrow + rr * 8;
                    float v0 = acc2[mi][ni][rr * 2 + 0];
                    float v1 = acc2[mi][ni][rr * 2 + 1];
                    __half h0, lo0, h1, lo1;
                    split2(v0, h0, lo0);
                    split2(v1, h1, lo1);
                    size_t o = ((size_t)(b * TT + t) * CC + h * 64 + n) >> 1;
                    ((uint32_t*)g_aoh)[o] = pk(h0, h1);
                    ((uint32_t*)g_aol)[o] = pk(lo0, lo1);
                }
            }
        }
        __syncthreads();
    }
}

// ---------------------------------------------------------------------------
extern "C" void kernel_launch(void* const* d_in, const int* in_sizes, int n_in,
                              void* d_out, int out_size) {
    const float* x    = (const float*)d_in[0];
    const float* Wqkv = (const float*)d_in[1];
    const float* bqkv = (const float*)d_in[2];
    const float* Wout = (const float*)d_in[3];
    const float* bout = (const float*)d_in[4];
    float* out = (float*)d_out;

    cudaFuncSetAttribute(attn_kernel,
                         cudaFuncAttributeMaxDynamicSharedMemorySize, ATTN_SMEM);
    cudaFuncSetAttribute(hmma_gemm,
                         cudaFuncAttributeMaxDynamicSharedMemorySize, GEMM_SMEM);

    // 1) Split-f16 conversions
    conv_rows<<<(BB * TT * CC / 4 + 255) / 256, 256>>>(x, BB * TT * CC / 4);
    conv_tr<<<dim3(3 * CC / 32, CC / 32), dim3(32, 8)>>>(Wqkv, CC, 3 * CC, 0);
    conv_tr<<<dim3(CC / 32, CC / 32), dim3(32, 8)>>>(Wout, CC, CC, 1);

    // 2) QKV projection -> q,k (2-way f16), v (fp32); ALSO generates the
    //    regrow bitmask as ALU filler under the tensor-pipe MMAs.
    hmma_gemm<<<dim3(3 * CC / 128, BB * TT / 128), 256, GEMM_SMEM>>>(
        bqkv, nullptr, 0);

    // 2b) V -> V^T f16 hi/lo
    vt_split<<<dim3(DD / 32, TT / 32, BB * HH), dim3(32, 8)>>>();

    // 3) Attention (pass1 HMMA QK + fragment softmax, pass2 HMMA AV)
    attn_kernel<<<dim3(TT / 256, HH, BB), 256, ATTN_SMEM>>>();

    // 4) Output projection
    hmma_gemm<<<dim3(CC / 128, BB * TT / 128), 256, GEMM_SMEM>>>(
        bout, out, 1);
}

// round 15
// speedup vs baseline: 1.0753x; 1.0753x over previous
#include <cuda_runtime.h>
#include <cuda_fp16.h>
#include <stdint.h>

#define BB 2
#define TT 2048
#define CC 1024
#define HH 16
#define DD 64

// ---------------------------------------------------------------------------
// Scratch (allocation-free rule: __device__ globals). Device-code refs only.
// ---------------------------------------------------------------------------
__device__ float g_v[BB * HH * TT * DD];
__device__ uint32_t g_mask[(size_t)BB * HH * TT * (TT / 32)];
// q, k in 2-way f16 decomposition (h + l ~ fp32): [bh][t][d]
__device__ __half g_qh[BB * HH * TT * DD], g_ql[BB * HH * TT * DD];
__device__ __half g_kh[BB * HH * TT * DD], g_kl[BB * HH * TT * DD];
// split-f16 GEMM operands
__device__ __half g_xh[BB * TT * CC], g_xl[BB * TT * CC];
__device__ __half g_wqh[3 * CC * CC], g_wql[3 * CC * CC];
__device__ __half g_woh[CC * CC], g_wol[CC * CC];
__device__ __half g_aoh[BB * TT * CC], g_aol[BB * TT * CC];
// V transposed per (b,h): [bh][d][t], f16 hi/lo
__device__ __half g_vth[(size_t)BB * HH * DD * TT];
__device__ __half g_vtl[(size_t)BB * HH * DD * TT];

// ---------------------------------------------------------------------------
// sm_80-level PTX helpers
// ---------------------------------------------------------------------------
__device__ __forceinline__ uint32_t smem_u32(const void* p) {
    uint32_t a;
    asm("{ .reg .u64 t; cvta.to.shared.u64 t, %1; cvt.u32.u64 %0, t; }"
        : "=r"(a) : "l"(p));
    return a;
}
__device__ __forceinline__ void cp16(uint32_t dst, const void* src) {
    asm volatile("cp.async.cg.shared.global [%0], [%1], 16;"
                 :: "r"(dst), "l"(src) : "memory");
}
#define CP_COMMIT() asm volatile("cp.async.commit_group;" ::: "memory")
#define CP_WAIT(n)  asm volatile("cp.async.wait_group %0;" :: "n"(n) : "memory")

// f16 x f16 -> f32 accumulate MMA
__device__ __forceinline__ void mma16816(float* c, const uint32_t* a,
                                         const uint32_t* b) {
    asm volatile(
        "mma.sync.aligned.m16n8k16.row.col.f32.f16.f16.f32 "
        "{%0,%1,%2,%3},{%4,%5,%6,%7},{%8,%9},{%0,%1,%2,%3};"
        : "+f"(c[0]), "+f"(c[1]), "+f"(c[2]), "+f"(c[3])
        : "r"(a[0]), "r"(a[1]), "r"(a[2]), "r"(a[3]), "r"(b[0]), "r"(b[1]));
}
__device__ __forceinline__ uint32_t pk(__half a, __half b) {
    return (uint32_t)__half_as_ushort(a) |
           ((uint32_t)__half_as_ushort(b) << 16);
}
__device__ __forceinline__ void split2(float v, __half& h, __half& l) {
    h = __float2half_rn(v);
    l = __float2half_rn(v - __half2float(h));
}

// ---------------------------------------------------------------------------
// Threefry-2x32, key = (0, 42)
// ---------------------------------------------------------------------------
__device__ __forceinline__ uint2 threefry_0_42(uint32_t x0, uint32_t x1) {
    const uint32_t ks0 = 0u, ks1 = 42u;
    const uint32_t ks2 = 0x1BD11BDAu ^ ks0 ^ ks1;
    x0 += ks0; x1 += ks1;
#define TF_RND(rot) { x0 += x1; x1 = __funnelshift_l(x1, x1, (rot)); x1 ^= x0; }
    TF_RND(13) TF_RND(15) TF_RND(26) TF_RND(6)
    x0 += ks1; x1 += ks2 + 1u;
    TF_RND(17) TF_RND(29) TF_RND(16) TF_RND(24)
    x0 += ks2; x1 += ks0 + 2u;
    TF_RND(13) TF_RND(15) TF_RND(26) TF_RND(6)
    x0 += ks0; x1 += ks1 + 3u;
    TF_RND(17) TF_RND(29) TF_RND(16) TF_RND(24)
    x0 += ks1; x1 += ks2 + 4u;
    TF_RND(13) TF_RND(15) TF_RND(26) TF_RND(6)
    x0 += ks2; x1 += ks0 + 5u;
#undef TF_RND
    return make_uint2(x0, x1);
}
__device__ __forceinline__ bool regrow_test(uint32_t idx) {
    uint2 rb = threefry_0_42(0u, idx);
    return ((rb.x ^ rb.y) >> 9) <= 419430u;
}

// Standalone mask kernel (two independent threefry chains per thread, ILP 2).
__global__ void __launch_bounds__(256)
mask_kernel() {
    const int t  = blockIdx.y;
    const int bh = blockIdx.z;
    const int wid = threadIdx.x >> 5, lane = threadIdx.x & 31;
    const int w0 = (blockIdx.x * 8 + wid) * 2;
    if (w0 * 32 > t) return;
    const uint32_t base = ((uint32_t)(bh * TT + t)) * (uint32_t)TT;
    bool r0 = regrow_test(base + (uint32_t)(w0 * 32 + lane));
    bool r1 = regrow_test(base + (uint32_t)(w0 * 32 + 32 + lane));
    uint32_t b0 = __ballot_sync(0xffffffffu, r0);
    uint32_t b1 = __ballot_sync(0xffffffffu, r1);
    if (lane == 0) {
        size_t o = ((size_t)(bh * TT + t)) * (TT / 32) + w0;
        g_mask[o] = b0;
        if ((w0 + 1) * 32 <= t) g_mask[o + 1] = b1;
    }
}

// ---------------------------------------------------------------------------
// fp32 -> f16 hi/lo split: x -> g_xh/g_xl
// ---------------------------------------------------------------------------
__global__ void __launch_bounds__(256)
conv_rows(const float* __restrict__ X, int n4) {
    int i = blockIdx.x * 256 + threadIdx.x;
    if (i >= n4) return;
    float4 v = ((const float4*)X)[i];
    float vv[4] = {v.x, v.y, v.z, v.w};
    __half h[4], l[4];
#pragma unroll
    for (int j = 0; j < 4; j++) split2(vv[j], h[j], l[j]);
    ((uint32_t*)g_xh)[i * 2]     = pk(h[0], h[1]);
    ((uint32_t*)g_xh)[i * 2 + 1] = pk(h[2], h[3]);
    ((uint32_t*)g_xl)[i * 2]     = pk(l[0], l[1]);
    ((uint32_t*)g_xl)[i * 2 + 1] = pk(l[2], l[3]);
}

// W [K][N] fp32 -> W^T [N][K] f16 hi/lo.  sel 0: g_wqh/g_wql, 1: g_woh/g_wol
__global__ void __launch_bounds__(256)
conv_tr(const float* __restrict__ W, int K, int N, int sel) {
    __shared__ float sm[32][33];
    __half* Th = (sel == 0) ? g_wqh : g_woh;
    __half* Tl = (sel == 0) ? g_wql : g_wol;
    const int n0 = blockIdx.x * 32, k0 = blockIdx.y * 32;
    const int tx = threadIdx.x, ty = threadIdx.y;
#pragma unroll
    for (int i = 0; i < 4; i++)
        sm[ty + i * 8][tx] = W[(size_t)(k0 + ty + i * 8) * N + n0 + tx];
    __syncthreads();
#pragma unroll
    for (int i = 0; i < 4; i++) {
        float v = sm[tx][ty + i * 8];
        __half h, l;
        split2(v, h, l);
        size_t o = (size_t)(n0 + ty + i * 8) * K + k0 + tx;
        Th[o] = h; Tl[o] = l;
    }
}

// g_v [bh][t][d] fp32 -> g_vth/g_vtl [bh][d][t] f16 hi/lo
__global__ void __launch_bounds__(256)
vt_split() {
    __shared__ float sm[32][33];
    const int bh = blockIdx.z;
    const int d0 = blockIdx.x * 32;
    const int t0 = blockIdx.y * 32;
    const int tx = threadIdx.x, ty = threadIdx.y;
    const float* src = g_v + (size_t)bh * TT * DD;
#pragma unroll
    for (int i = 0; i < 4; i++)
        sm[ty + i * 8][tx] = src[(size_t)(t0 + ty + i * 8) * DD + d0 + tx];
    __syncthreads();
#pragma unroll
    for (int i = 0; i < 4; i++) {
        float v = sm[tx][ty + i * 8];
        __half h, l;
        split2(v, h, l);
        size_t o = ((size_t)bh * DD + d0 + ty + i * 8) * TT + t0 + tx;
        g_vth[o] = h; g_vtl[o] = l;
    }
}

// ---------------------------------------------------------------------------
// Split-f16 HMMA GEMM (clean R13 version): C = A @ Bt^T + bias.
//   sel 0: A=g_xh/g_xl, Bt=g_wqh/g_wql; scatter q,k as 2-way f16, v fp32.
//   sel 1: A=g_aoh/g_aol, Bt=g_woh/g_wol; row-major store to Cout.
// ---------------------------------------------------------------------------
#define GOPE   (128 * 40)
#define GSTAGE (4 * GOPE)
#define GEMM_SMEM (2 * GSTAGE * 2)

__global__ void __launch_bounds__(256)
hmma_gemm(const float* __restrict__ bias, float* __restrict__ Cout, int sel) {
    extern __shared__ __half gsm[];
    const __half* Ah = (sel == 0) ? g_xh : g_aoh;
    const __half* Al = (sel == 0) ? g_xl : g_aol;
    const __half* Bh = (sel == 0) ? g_wqh : g_woh;
    const __half* Bl = (sel == 0) ? g_wql : g_wol;
    const int Kdim = CC;
    const int Ncols = (sel == 0) ? 3 * CC : CC;

    const int tid = threadIdx.x;
    const int lane = tid & 31, wid = tid >> 5;
    const int wm = wid & 3, wn = wid >> 2;
    const int n0 = blockIdx.x * 128, m0 = blockIdx.y * 128;
    const int g = lane >> 2, j2 = (lane & 3) * 2;

    float acc[2][8][4];
#pragma unroll
    for (int mi = 0; mi < 2; mi++)
#pragma unroll
        for (int ni = 0; ni < 8; ni++)
#pragma unroll
            for (int r = 0; r < 4; r++) acc[mi][ni][r] = 0.f;

    const int nch = Kdim / 32;

#define ISSUE_LOADS(IT, STAGE) do {                                          \
        const int _k0 = (IT) * 32;                                          \
        __half* _sb = gsm + (STAGE) * GSTAGE;                               \
        _Pragma("unroll")                                                    \
        for (int _r = 0; _r < 2; _r++) {                                     \
            int _c = _r * 256 + tid;                                         \
            int _row = _c >> 2, _off = (_c & 3) * 8;                         \
            uint32_t _so = smem_u32(_sb + _row * 40 + _off);                 \
            size_t _ga = (size_t)(m0 + _row) * Kdim + _k0 + _off;            \
            size_t _gb = (size_t)(n0 + _row) * Kdim + _k0 + _off;            \
            cp16(_so,                 Ah + _ga);                             \
            cp16(_so + 2 * GOPE,      Al + _ga);                             \
            cp16(_so + 4 * GOPE,      Bh + _gb);                             \
            cp16(_so + 6 * GOPE,      Bl + _gb);                             \
        }                                                                    \
    } while (0)

    ISSUE_LOADS(0, 0);
    CP_COMMIT();

    for (int it = 0; it < nch; it++) {
        if (it + 1 < nch) {
            ISSUE_LOADS(it + 1, (it + 1) & 1);
            CP_COMMIT();
            CP_WAIT(1);
        } else {
            CP_WAIT(0);
        }
        __syncthreads();

        const __half* sAh = gsm + (it & 1) * GSTAGE;
        const __half* sAl = sAh + GOPE;
        const __half* sBh = sAh + 2 * GOPE;
        const __half* sBl = sAh + 3 * GOPE;

#pragma unroll
        for (int ks = 0; ks < 2; ks++) {
            const int k0 = ks * 16;
            uint32_t ah[2][4], al[2][4], bh[8][2], bl[8][2];
#pragma unroll
            for (int mi = 0; mi < 2; mi++) {
                int row = wm * 32 + mi * 16;
                ah[mi][0] = *(const uint32_t*)&sAh[(row + g) * 40 + k0 + j2];
                ah[mi][1] = *(const uint32_t*)&sAh[(row + 8 + g) * 40 + k0 + j2];
                ah[mi][2] = *(const uint32_t*)&sAh[(row + g) * 40 + k0 + j2 + 8];
                ah[mi][3] = *(const uint32_t*)&sAh[(row + 8 + g) * 40 + k0 + j2 + 8];
                al[mi][0] = *(const uint32_t*)&sAl[(row + g) * 40 + k0 + j2];
                al[mi][1] = *(const uint32_t*)&sAl[(row + 8 + g) * 40 + k0 + j2];
                al[mi][2] = *(const uint32_t*)&sAl[(row + g) * 40 + k0 + j2 + 8];
                al[mi][3] = *(const uint32_t*)&sAl[(row + 8 + g) * 40 + k0 + j2 + 8];
            }
#pragma unroll
            for (int ni = 0; ni < 8; ni++) {
                int n = wn * 64 + ni * 8 + g;
                bh[ni][0] = *(const uint32_t*)&sBh[n * 40 + k0 + j2];
                bh[ni][1] = *(const uint32_t*)&sBh[n * 40 + k0 + j2 + 8];
                bl[ni][0] = *(const uint32_t*)&sBl[n * 40 + k0 + j2];
                bl[ni][1] = *(const uint32_t*)&sBl[n * 40 + k0 + j2 + 8];
            }
#pragma unroll
            for (int mi = 0; mi < 2; mi++)
#pragma unroll
                for (int ni = 0; ni < 8; ni++) {
                    mma16816(acc[mi][ni], ah[mi], bh[ni]);
                    mma16816(acc[mi][ni], ah[mi], bl[ni]);
                    mma16816(acc[mi][ni], al[mi], bh[ni]);
                }
        }
        __syncthreads();
    }

#pragma unroll
    for (int mi = 0; mi < 2; mi++) {
#pragma unroll
        for (int ni = 0; ni < 8; ni++) {
            int m_r = m0 + wm * 32 + mi * 16 + g;
            int n_c = n0 + wn * 64 + ni * 8 + j2;
            float b0 = bias[n_c], b1 = bias[n_c + 1];
            float v00 = acc[mi][ni][0] + b0, v01 = acc[mi][ni][1] + b1;
            float v10 = acc[mi][ni][2] + b0, v11 = acc[mi][ni][3] + b1;
            if (sel == 1) {
                *(float2*)&Cout[(size_t)m_r * Ncols + n_c] = make_float2(v00, v01);
                *(float2*)&Cout[(size_t)(m_r + 8) * Ncols + n_c] = make_float2(v10, v11);
            } else {
                int part = n_c >> 10, rem = n_c & 1023;
                int hh = rem >> 6, dd = rem & 63;
                int b = m_r >> 11, t = m_r & 2047;
                int b2 = (m_r + 8) >> 11, t2 = (m_r + 8) & 2047;
                size_t o1 = (((size_t)b * HH + hh) * TT + t) * DD + dd;
                size_t o2 = (((size_t)b2 * HH + hh) * TT + t2) * DD + dd;
                if (part == 2) {
                    *(float2*)&g_v[o1] = make_float2(v00, v01);
                    *(float2*)&g_v[o2] = make_float2(v10, v11);
                } else {
                    __half* AH = (part == 0) ? g_qh : g_kh;
                    __half* AL = (part == 0) ? g_ql : g_kl;
                    __half h0, l0, h1, l1;
                    split2(v00, h0, l0);
                    split2(v01, h1, l1);
                    ((uint32_t*)AH)[o1 >> 1] = pk(h0, h1);
                    ((uint32_t*)AL)[o1 >> 1] = pk(l0, l1);
                    split2(v10, h0, l0);
                    split2(v11, h1, l1);
                    ((uint32_t*)AH)[o2 >> 1] = pk(h0, h1);
                    ((uint32_t*)AL)[o2 >> 1] = pk(l0, l1);
                }
            }
        }
    }
#undef ISSUE_LOADS
}

// ---------------------------------------------------------------------------
// Attention, recompute-QK variant (no e cache, no g_mh).
// Pass 1: QK HMMA + fragment softmax reductions only -> m,l in registers.
// Pass 2: QK HMMA again (bit-identical), p = exp(s - m_fin)*inv_l computed on
//         fragments, threshold||regrow, split -> a_sm, AV HMMA.
// smem (110592 B, 2 blocks/SM):
//   stgK [0,36864) 2 stages | stgV [36864,73728) 2 stages |
//   q2 [73728,110592)  (pass 1)  ALIAS  a_h [73728,92160)+a_l [92160,110592)
// ---------------------------------------------------------------------------
#define ATTN_SMEM 110592

__global__ void __launch_bounds__(256, 2)
attn_kernel() {
    extern __shared__ char asmem[];
    __half* stgK = (__half*)asmem;                 // 2 x 18432 B
    __half* stgV = (__half*)(asmem + 36864);       // 2 x 18432 B
    __half* q_sm = (__half*)(asmem + 73728);       // 36864 B (pass 1)
    __half* a_smh = (__half*)(asmem + 73728);      // 18432 B (pass 2)
    __half* a_sml = (__half*)(asmem + 92160);      // 18432 B (pass 2)

    const int NQB = TT / 128;
    const int bh = blockIdx.z * HH + blockIdx.y;
    const int tid = threadIdx.x;
    const int lane = tid & 31, wid = tid >> 5;
    const int wm = wid & 3, wn = wid >> 2;
    const int g = lane >> 2, qd = lane & 3, j2 = qd * 2;

    const uint32_t* qh32 = (const uint32_t*)q_sm;
    const uint32_t* ql32 = qh32 + 4608;

    for (int half = 0; half < 2; half++) {
        const int qb = half == 0 ? (NQB - 1 - (int)blockIdx.x) : (int)blockIdx.x;
        const int t0 = qb * 128;
        const int ntiles = 2 * qb + 2;

        // ---- stage q2 via cp.async (2048 chunks, 8/thread) ----
#pragma unroll
        for (int rep = 0; rep < 8; rep++) {
            int c = rep * 256 + tid;
            int arr = c >> 10, cc = c & 1023, row = cc >> 3, j = cc & 7;
            const __half* src = (arr == 0 ? g_qh : g_ql) +
                ((size_t)bh * TT + t0 + row) * DD + j * 8;
            cp16(smem_u32(q_sm + arr * 9216 + row * 72 + j * 8), src);
        }
        CP_COMMIT();
        // ---- stage k2 tile 0 ----
#pragma unroll
        for (int rep = 0; rep < 4; rep++) {
            int c = rep * 256 + tid;
            int arr = c >> 9, cc = c & 511, row = cc >> 3, j = cc & 7;
            const __half* src = (arr == 0 ? g_kh : g_kl) +
                ((size_t)bh * TT + row) * DD + j * 8;
            cp16(smem_u32(stgK + arr * 4608 + row * 72 + j * 8), src);
        }
        CP_COMMIT();
        CP_WAIT(1);
        __syncthreads();

        // ---- Q fragments in registers (held across both passes) ----
        uint32_t qfh[4][4], qfl[4][4];
#pragma unroll
        for (int ks = 0; ks < 4; ks++) {
            int b0 = (16 * wid + g) * 36 + ks * 8 + qd;
            int b1 = b0 + 8 * 36;
            qfh[ks][0] = qh32[b0]; qfh[ks][1] = qh32[b1];
            qfh[ks][2] = qh32[b0 + 4]; qfh[ks][3] = qh32[b1 + 4];
            qfl[ks][0] = ql32[b0]; qfl[ks][1] = ql32[b1];
            qfl[ks][2] = ql32[b0 + 4]; qfl[ks][3] = ql32[b1 + 4];
        }

        const int r0 = 16 * wid + g, r1 = r0 + 8;
        const int tg0 = t0 + r0, tg1 = t0 + r1;
        float m0 = -1e30f, m1 = -1e30f, l0 = 0.f, l1 = 0.f;

        // ---------------- Pass 1: reductions only ----------------
        for (int it = 0; it < ntiles; it++) {
            const int s0 = it * 64;
            CP_WAIT(0);
            __syncthreads();
            if (it + 1 < ntiles) {
                __half* stn = stgK + ((it + 1) & 1) * 9216;
#pragma unroll
                for (int rep = 0; rep < 4; rep++) {
                    int c = rep * 256 + tid;
                    int arr = c >> 9, cc = c & 511, row = cc >> 3, j = cc & 7;
                    const __half* src = (arr == 0 ? g_kh : g_kl) +
                        ((size_t)bh * TT + s0 + 64 + row) * DD + j * 8;
                    cp16(smem_u32(stn + arr * 4608 + row * 72 + j * 8), src);
                }
                CP_COMMIT();
            }

            const uint32_t* kh32s =
                (const uint32_t*)(stgK + (it & 1) * 9216);
            const uint32_t* kl32s = kh32s + 2304;

            float acc[8][4];
#pragma unroll
            for (int ni = 0; ni < 8; ni++)
#pragma unroll
                for (int r = 0; r < 4; r++) acc[ni][r] = 0.f;
#pragma unroll
            for (int ks = 0; ks < 4; ks++) {
#pragma unroll
                for (int ni = 0; ni < 8; ni++) {
                    int bb = (ni * 8 + g) * 36 + ks * 8 + qd;
                    uint32_t b_h[2] = {kh32s[bb], kh32s[bb + 4]};
                    uint32_t b_l[2] = {kl32s[bb], kl32s[bb + 4]};
                    mma16816(acc[ni], qfh[ks], b_h);
                    mma16816(acc[ni], qfl[ks], b_h);
                    mma16816(acc[ni], qfh[ks], b_l);
                }
            }

            float tm0 = -1e30f, tm1 = -1e30f;
#pragma unroll
            for (int ni = 0; ni < 8; ni++) {
                int s = s0 + ni * 8 + j2;
                acc[ni][0] = (s     <= tg0) ? acc[ni][0] * 0.125f : -1e30f;
                acc[ni][1] = (s + 1 <= tg0) ? acc[ni][1] * 0.125f : -1e30f;
                acc[ni][2] = (s     <= tg1) ? acc[ni][2] * 0.125f : -1e30f;
                acc[ni][3] = (s + 1 <= tg1) ? acc[ni][3] * 0.125f : -1e30f;
                tm0 = fmaxf(tm0, fmaxf(acc[ni][0], acc[ni][1]));
                tm1 = fmaxf(tm1, fmaxf(acc[ni][2], acc[ni][3]));
            }
            tm0 = fmaxf(tm0, __shfl_xor_sync(0xffffffffu, tm0, 1));
            tm0 = fmaxf(tm0, __shfl_xor_sync(0xffffffffu, tm0, 2));
            tm1 = fmaxf(tm1, __shfl_xor_sync(0xffffffffu, tm1, 1));
            tm1 = fmaxf(tm1, __shfl_xor_sync(0xffffffffu, tm1, 2));
            float mn0 = fmaxf(m0, tm0), mn1 = fmaxf(m1, tm1);
            float ls0 = 0.f, ls1 = 0.f;
#pragma unroll
            for (int ni = 0; ni < 8; ni++) {
                ls0 += __expf(acc[ni][0] - mn0) + __expf(acc[ni][1] - mn0);
                ls1 += __expf(acc[ni][2] - mn1) + __expf(acc[ni][3] - mn1);
            }
            ls0 += __shfl_xor_sync(0xffffffffu, ls0, 1);
            ls0 += __shfl_xor_sync(0xffffffffu, ls0, 2);
            ls1 += __shfl_xor_sync(0xffffffffu, ls1, 1);
            ls1 += __shfl_xor_sync(0xffffffffu, ls1, 2);
            l0 = l0 * __expf(m0 - mn0) + ls0; m0 = mn0;
            l1 = l1 * __expf(m1 - mn1) + ls1; m1 = mn1;
        }

        const float invl0 = 1.0f / l0, invl1 = 1.0f / l1;
        const size_t mrow0 = ((size_t)(bh * TT + tg0)) * (TT / 32);
        const size_t mrow1 = ((size_t)(bh * TT + tg1)) * (TT / 32);

        // ---- re-stage k0 + vt0 for pass 2 ----
        __syncthreads();
#pragma unroll
        for (int rep = 0; rep < 4; rep++) {
            int c = rep * 256 + tid;
            int arr = c >> 9, cc = c & 511, row = cc >> 3, j = cc & 7;
            const __half* srck = (arr == 0 ? g_kh : g_kl) +
                ((size_t)bh * TT + row) * DD + j * 8;
            cp16(smem_u32(stgK + arr * 4608 + row * 72 + j * 8), srck);
            const __half* srcv = (arr ? g_vtl : g_vth) +
                ((size_t)bh * DD + row) * TT + j * 8;
            cp16(smem_u32(stgV + arr * 4608 + row * 72 + j * 8), srcv);
        }
        CP_COMMIT();

        // ---------------- Pass 2: recompute, sparsify, AV ----------------
        float acc2[2][4][4];
#pragma unroll
        for (int mi = 0; mi < 2; mi++)
#pragma unroll
            for (int ni = 0; ni < 4; ni++)
#pragma unroll
                for (int r = 0; r < 4; r++) acc2[mi][ni][r] = 0.f;

        for (int it = 0; it < ntiles; it++) {
            const int s0 = it * 64;
            CP_WAIT(0);
            __syncthreads();
            if (it + 1 < ntiles) {
                __half* stnK = stgK + ((it + 1) & 1) * 9216;
                __half* stnV = stgV + ((it + 1) & 1) * 9216;
#pragma unroll
                for (int rep = 0; rep < 4; rep++) {
                    int c = rep * 256 + tid;
                    int arr = c >> 9, cc = c & 511, row = cc >> 3, j = cc & 7;
                    const __half* srck = (arr == 0 ? g_kh : g_kl) +
                        ((size_t)bh * TT + s0 + 64 + row) * DD + j * 8;
                    cp16(smem_u32(stnK + arr * 4608 + row * 72 + j * 8), srck);
                    const __half* srcv = (arr ? g_vtl : g_vth) +
                        ((size_t)bh * DD + row) * TT + s0 + 64 + j * 8;
                    cp16(smem_u32(stnV + arr * 4608 + row * 72 + j * 8), srcv);
                }
                CP_COMMIT();
            }

            // QK recompute (bit-identical to pass 1)
            const uint32_t* kh32s =
                (const uint32_t*)(stgK + (it & 1) * 9216);
            const uint32_t* kl32s = kh32s + 2304;
            float acc[8][4];
#pragma unroll
            for (int ni = 0; ni < 8; ni++)
#pragma unroll
                for (int r = 0; r < 4; r++) acc[ni][r] = 0.f;
#pragma unroll
            for (int ks = 0; ks < 4; ks++) {
#pragma unroll
                for (int ni = 0; ni < 8; ni++) {
                    int bb = (ni * 8 + g) * 36 + ks * 8 + qd;
                    uint32_t b_h[2] = {kh32s[bb], kh32s[bb + 4]};
                    uint32_t b_l[2] = {kl32s[bb], kl32s[bb + 4]};
                    mma16816(acc[ni], qfh[ks], b_h);
                    mma16816(acc[ni], qfl[ks], b_h);
                    mma16816(acc[ni], qfh[ks], b_l);
                }
            }

            // p = exp(s - m_fin) * inv_l on fragments; threshold || regrow
            uint32_t w00 = g_mask[mrow0 + (s0 >> 5)];
            uint32_t w01 = g_mask[mrow0 + (s0 >> 5) + 1];
            uint32_t w10 = g_mask[mrow1 + (s0 >> 5)];
            uint32_t w11 = g_mask[mrow1 + (s0 >> 5) + 1];
#pragma unroll
            for (int ni = 0; ni < 8; ni++) {
                int s = s0 + ni * 8 + j2;
                int bp = (ni * 8 + j2) & 31;
                uint32_t wa = (ni < 4) ? w00 : w01;
                uint32_t wb = (ni < 4) ? w10 : w11;
                float s00 = (s     <= tg0) ? acc[ni][0] * 0.125f : -1e30f;
                float s01 = (s + 1 <= tg0) ? acc[ni][1] * 0.125f : -1e30f;
                float s10 = (s     <= tg1) ? acc[ni][2] * 0.125f : -1e30f;
                float s11 = (s + 1 <= tg1) ? acc[ni][3] * 0.125f : -1e30f;
                float p00 = __expf(s00 - m0) * invl0;
                float p01 = __expf(s01 - m0) * invl0;
                float p10 = __expf(s10 - m1) * invl1;
                float p11 = __expf(s11 - m1) * invl1;
                p00 = (p00 > 0.01f || ((wa >> (bp + 0)) & 1u)) ? p00 : 0.f;
                p01 = (p01 > 0.01f || ((wa >> (bp + 1)) & 1u)) ? p01 : 0.f;
                p10 = (p10 > 0.01f || ((wb >> (bp + 0)) & 1u)) ? p10 : 0.f;
                p11 = (p11 > 0.01f || ((wb >> (bp + 1)) & 1u)) ? p11 : 0.f;
                __half h0, lo0, h1, lo1;
                split2(p00, h0, lo0); split2(p01, h1, lo1);
                ((uint32_t*)a_smh)[r0 * 36 + ni * 4 + qd] = pk(h0, h1);
                ((uint32_t*)a_sml)[r0 * 36 + ni * 4 + qd] = pk(lo0, lo1);
                split2(p10, h0, lo0); split2(p11, h1, lo1);
                ((uint32_t*)a_smh)[r1 * 36 + ni * 4 + qd] = pk(h0, h1);
                ((uint32_t*)a_sml)[r1 * 36 + ni * 4 + qd] = pk(lo0, lo1);
            }
            __syncthreads();

            // AV MMA
            const uint32_t* ah32 = (const uint32_t*)a_smh;
            const uint32_t* al32 = (const uint32_t*)a_sml;
            const uint32_t* vh32 =
                (const uint32_t*)(stgV + (it & 1) * 9216);
            const uint32_t* vl32 = vh32 + 2304;
#pragma unroll
            for (int ks = 0; ks < 4; ks++) {
                uint32_t ah[2][4], al[2][4], bh[4][2], bl[4][2];
#pragma unroll
                for (int mi = 0; mi < 2; mi++) {
                    int base = (wm * 32 + mi * 16 + g) * 36 + ks * 8 + qd;
                    ah[mi][0] = ah32[base];
                    ah[mi][1] = ah32[base + 8 * 36];
                    ah[mi][2] = ah32[base + 4];
                    ah[mi][3] = ah32[base + 8 * 36 + 4];
                    al[mi][0] = al32[base];
                    al[mi][1] = al32[base + 8 * 36];
                    al[mi][2] = al32[base + 4];
                    al[mi][3] = al32[base + 8 * 36 + 4];
                }
#pragma unroll
                for (int ni = 0; ni < 4; ni++) {
                    int base = (wn * 32 + ni * 8 + g) * 36 + ks * 8 + qd;
                    bh[ni][0] = vh32[base];
                    bh[ni][1] = vh32[base + 4];
                    bl[ni][0] = vl32[base];
                    bl[ni][1] = vl32[base + 4];
                }
#pragma unroll
                for (int mi = 0; mi < 2; mi++)
#pragma unroll
                    for (int ni = 0; ni < 4; ni++) {
                        mma16816(acc2[mi][ni], ah[mi], bh[ni]);
                        mma16816(acc2[mi][ni], ah[mi], bl[ni]);
                        mma16816(acc2[mi][ni], al[mi], bh[ni]);
                    }
            }
        }

        // epilogue: split output, write g_aoh/g_aol directly
        const int b = blockIdx.z, h = blockIdx.y;
#pragma unroll
        for (int mi = 0; mi < 2; mi++) {
#pragma unroll
            for (int ni = 0; ni < 4; ni++) {
                int mrow = wm * 32 + mi * 16 + g;
                int n = wn * 32 + ni * 8 + j2;
#pragma unroll
                for (int rr = 0; rr < 2; rr++) {
                    int t = t0 + mrow + rr * 8;
                    float v0 = acc2[mi][ni][rr * 2 + 0];
                    float v1 = acc2[mi][ni][rr * 2 + 1];
                    __half h0, lo0, h1, lo1;
                    split2(v0, h0, lo0);
                    split2(v1, h1, lo1);
                    size_t o = ((size_t)(b * TT + t) * CC + h * 64 + n) >> 1;
                    ((uint32_t*)g_aoh)[o] = pk(h0, h1);
                    ((uint32_t*)g_aol)[o] = pk(lo0, lo1);
                }
            }
        }
        __syncthreads();
    }
}

// ---------------------------------------------------------------------------
extern "C" void kernel_launch(void* const* d_in, const int* in_sizes, int n_in,
                              void* d_out, int out_size) {
    const float* x    = (const float*)d_in[0];
    const float* Wqkv = (const float*)d_in[1];
    const float* bqkv = (const float*)d_in[2];
    const float* Wout = (const float*)d_in[3];
    const float* bout = (const float*)d_in[4];
    float* out = (float*)d_out;

    cudaFuncSetAttribute(attn_kernel,
                         cudaFuncAttributeMaxDynamicSharedMemorySize, ATTN_SMEM);
    cudaFuncSetAttribute(hmma_gemm,
                         cudaFuncAttributeMaxDynamicSharedMemorySize, GEMM_SMEM);

    // 0) Regrow bitmask (input-independent, standalone)
    mask_kernel<<<dim3(4, TT, BB * HH), 256>>>();

    // 1) Split-f16 conversions
    conv_rows<<<(BB * TT * CC / 4 + 255) / 256, 256>>>(x, BB * TT * CC / 4);
    conv_tr<<<dim3(3 * CC / 32, CC / 32), dim3(32, 8)>>>(Wqkv, CC, 3 * CC, 0);
    conv_tr<<<dim3(CC / 32, CC / 32), dim3(32, 8)>>>(Wout, CC, CC, 1);

    // 2) QKV projection -> q,k (2-way f16), v (fp32)
    hmma_gemm<<<dim3(3 * CC / 128, BB * TT / 128), 256, GEMM_SMEM>>>(
        bqkv, nullptr, 0);

    // 2b) V -> V^T f16 hi/lo
    vt_split<<<dim3(DD / 32, TT / 32, BB * HH), dim3(32, 8)>>>();

    // 3) Attention (recompute-QK, no e cache)
    attn_kernel<<<dim3(TT / 256, HH, BB), 256, ATTN_SMEM>>>();

    // 4) Output projection
    hmma_gemm<<<dim3(CC / 128, BB * TT / 128), 256, GEMM_SMEM>>>(
        bout, out, 1);
}

// round 16
// speedup vs baseline: 1.1064x; 1.0289x over previous
#include <cuda_runtime.h>
#include <cuda_fp16.h>
#include <stdint.h>

#define BB 2
#define TT 2048
#define CC 1024
#define HH 16
#define DD 64

// ---------------------------------------------------------------------------
// Scratch (allocation-free rule: __device__ globals). Device-code refs only.
// ---------------------------------------------------------------------------
__device__ float g_v[BB * HH * TT * DD];
__device__ uint32_t g_mask[(size_t)BB * HH * TT * (TT / 32)];
// q, k in 2-way f16 decomposition (h + l ~ fp32): [bh][t][d]
__device__ __half g_qh[BB * HH * TT * DD], g_ql[BB * HH * TT * DD];
__device__ __half g_kh[BB * HH * TT * DD], g_kl[BB * HH * TT * DD];
// split-f16 GEMM operands
__device__ __half g_xh[BB * TT * CC], g_xl[BB * TT * CC];
__device__ __half g_wqh[3 * CC * CC], g_wql[3 * CC * CC];
__device__ __half g_woh[CC * CC], g_wol[CC * CC];
__device__ __half g_aoh[BB * TT * CC], g_aol[BB * TT * CC];
// V transposed per (b,h): [bh][d][t], f16 hi/lo
__device__ __half g_vth[(size_t)BB * HH * DD * TT];
__device__ __half g_vtl[(size_t)BB * HH * DD * TT];

// ---------------------------------------------------------------------------
// sm_80-level PTX helpers
// ---------------------------------------------------------------------------
__device__ __forceinline__ uint32_t smem_u32(const void* p) {
    uint32_t a;
    asm("{ .reg .u64 t; cvta.to.shared.u64 t, %1; cvt.u32.u64 %0, t; }"
        : "=r"(a) : "l"(p));
    return a;
}
__device__ __forceinline__ void cp16(uint32_t dst, const void* src) {
    asm volatile("cp.async.cg.shared.global [%0], [%1], 16;"
                 :: "r"(dst), "l"(src) : "memory");
}
#define CP_COMMIT() asm volatile("cp.async.commit_group;" ::: "memory")
#define CP_WAIT(n)  asm volatile("cp.async.wait_group %0;" :: "n"(n) : "memory")

// f16 x f16 -> f32 accumulate MMA
__device__ __forceinline__ void mma16816(float* c, const uint32_t* a,
                                         const uint32_t* b) {
    asm volatile(
        "mma.sync.aligned.m16n8k16.row.col.f32.f16.f16.f32 "
        "{%0,%1,%2,%3},{%4,%5,%6,%7},{%8,%9},{%0,%1,%2,%3};"
        : "+f"(c[0]), "+f"(c[1]), "+f"(c[2]), "+f"(c[3])
        : "r"(a[0]), "r"(a[1]), "r"(a[2]), "r"(a[3]), "r"(b[0]), "r"(b[1]));
}
// ldmatrix x4: loads 4 8x8 b16 tiles; lane L holds (row L>>2, col 2(L&3)) of
// each tile; lanes 0-7/8-15/16-23/24-31 supply row addresses of tiles 0..3.
__device__ __forceinline__ void ldm_x4(uint32_t* r, uint32_t addr) {
    asm volatile(
        "ldmatrix.sync.aligned.m8n8.x4.shared.b16 {%0,%1,%2,%3}, [%4];"
        : "=r"(r[0]), "=r"(r[1]), "=r"(r[2]), "=r"(r[3]) : "r"(addr));
}
__device__ __forceinline__ uint32_t pk(__half a, __half b) {
    return (uint32_t)__half_as_ushort(a) |
           ((uint32_t)__half_as_ushort(b) << 16);
}
__device__ __forceinline__ void split2(float v, __half& h, __half& l) {
    h = __float2half_rn(v);
    l = __float2half_rn(v - __half2float(h));
}

// ---------------------------------------------------------------------------
// Threefry-2x32, key = (0, 42)
// ---------------------------------------------------------------------------
__device__ __forceinline__ uint2 threefry_0_42(uint32_t x0, uint32_t x1) {
    const uint32_t ks0 = 0u, ks1 = 42u;
    const uint32_t ks2 = 0x1BD11BDAu ^ ks0 ^ ks1;
    x0 += ks0; x1 += ks1;
#define TF_RND(rot) { x0 += x1; x1 = __funnelshift_l(x1, x1, (rot)); x1 ^= x0; }
    TF_RND(13) TF_RND(15) TF_RND(26) TF_RND(6)
    x0 += ks1; x1 += ks2 + 1u;
    TF_RND(17) TF_RND(29) TF_RND(16) TF_RND(24)
    x0 += ks2; x1 += ks0 + 2u;
    TF_RND(13) TF_RND(15) TF_RND(26) TF_RND(6)
    x0 += ks0; x1 += ks1 + 3u;
    TF_RND(17) TF_RND(29) TF_RND(16) TF_RND(24)
    x0 += ks1; x1 += ks2 + 4u;
    TF_RND(13) TF_RND(15) TF_RND(26) TF_RND(6)
    x0 += ks2; x1 += ks0 + 5u;
#undef TF_RND
    return make_uint2(x0, x1);
}
__device__ __forceinline__ bool regrow_test(uint32_t idx) {
    uint2 rb = threefry_0_42(0u, idx);
    return ((rb.x ^ rb.y) >> 9) <= 419430u;
}

// Standalone mask kernel (two independent threefry chains per thread, ILP 2).
__global__ void __launch_bounds__(256)
mask_kernel() {
    const int t  = blockIdx.y;
    const int bh = blockIdx.z;
    const int wid = threadIdx.x >> 5, lane = threadIdx.x & 31;
    const int w0 = (blockIdx.x * 8 + wid) * 2;
    if (w0 * 32 > t) return;
    const uint32_t base = ((uint32_t)(bh * TT + t)) * (uint32_t)TT;
    bool r0 = regrow_test(base + (uint32_t)(w0 * 32 + lane));
    bool r1 = regrow_test(base + (uint32_t)(w0 * 32 + 32 + lane));
    uint32_t b0 = __ballot_sync(0xffffffffu, r0);
    uint32_t b1 = __ballot_sync(0xffffffffu, r1);
    if (lane == 0) {
        size_t o = ((size_t)(bh * TT + t)) * (TT / 32) + w0;
        g_mask[o] = b0;
        if ((w0 + 1) * 32 <= t) g_mask[o + 1] = b1;
    }
}

// ---------------------------------------------------------------------------
// fp32 -> f16 hi/lo split: x -> g_xh/g_xl
// ---------------------------------------------------------------------------
__global__ void __launch_bounds__(256)
conv_rows(const float* __restrict__ X, int n4) {
    int i = blockIdx.x * 256 + threadIdx.x;
    if (i >= n4) return;
    float4 v = ((const float4*)X)[i];
    float vv[4] = {v.x, v.y, v.z, v.w};
    __half h[4], l[4];
#pragma unroll
    for (int j = 0; j < 4; j++) split2(vv[j], h[j], l[j]);
    ((uint32_t*)g_xh)[i * 2]     = pk(h[0], h[1]);
    ((uint32_t*)g_xh)[i * 2 + 1] = pk(h[2], h[3]);
    ((uint32_t*)g_xl)[i * 2]     = pk(l[0], l[1]);
    ((uint32_t*)g_xl)[i * 2 + 1] = pk(l[2], l[3]);
}

// W [K][N] fp32 -> W^T [N][K] f16 hi/lo.  sel 0: g_wqh/g_wql, 1: g_woh/g_wol
__global__ void __launch_bounds__(256)
conv_tr(const float* __restrict__ W, int K, int N, int sel) {
    __shared__ float sm[32][33];
    __half* Th = (sel == 0) ? g_wqh : g_woh;
    __half* Tl = (sel == 0) ? g_wql : g_wol;
    const int n0 = blockIdx.x * 32, k0 = blockIdx.y * 32;
    const int tx = threadIdx.x, ty = threadIdx.y;
#pragma unroll
    for (int i = 0; i < 4; i++)
        sm[ty + i * 8][tx] = W[(size_t)(k0 + ty + i * 8) * N + n0 + tx];
    __syncthreads();
#pragma unroll
    for (int i = 0; i < 4; i++) {
        float v = sm[tx][ty + i * 8];
        __half h, l;
        split2(v, h, l);
        size_t o = (size_t)(n0 + ty + i * 8) * K + k0 + tx;
        Th[o] = h; Tl[o] = l;
    }
}

// g_v [bh][t][d] fp32 -> g_vth/g_vtl [bh][d][t] f16 hi/lo
__global__ void __launch_bounds__(256)
vt_split() {
    __shared__ float sm[32][33];
    const int bh = blockIdx.z;
    const int d0 = blockIdx.x * 32;
    const int t0 = blockIdx.y * 32;
    const int tx = threadIdx.x, ty = threadIdx.y;
    const float* src = g_v + (size_t)bh * TT * DD;
#pragma unroll
    for (int i = 0; i < 4; i++)
        sm[ty + i * 8][tx] = src[(size_t)(t0 + ty + i * 8) * DD + d0 + tx];
    __syncthreads();
#pragma unroll
    for (int i = 0; i < 4; i++) {
        float v = sm[tx][ty + i * 8];
        __half h, l;
        split2(v, h, l);
        size_t o = ((size_t)bh * DD + d0 + ty + i * 8) * TT + t0 + tx;
        g_vth[o] = h; g_vtl[o] = l;
    }
}

// ---------------------------------------------------------------------------
// Split-f16 HMMA GEMM with ldmatrix fragment loads: C = A @ Bt^T + bias.
//   sel 0: A=g_xh/g_xl, Bt=g_wqh/g_wql; scatter q,k as 2-way f16, v fp32.
//   sel 1: A=g_aoh/g_aol, Bt=g_woh/g_wol; row-major store to Cout.
// ---------------------------------------------------------------------------
#define GOPE   (128 * 40)
#define GSTAGE (4 * GOPE)
#define GEMM_SMEM (2 * GSTAGE * 2)

__global__ void __launch_bounds__(256)
hmma_gemm(const float* __restrict__ bias, float* __restrict__ Cout, int sel) {
    extern __shared__ __half gsm[];
    const __half* Ah = (sel == 0) ? g_xh : g_aoh;
    const __half* Al = (sel == 0) ? g_xl : g_aol;
    const __half* Bh = (sel == 0) ? g_wqh : g_woh;
    const __half* Bl = (sel == 0) ? g_wql : g_wol;
    const int Kdim = CC;
    const int Ncols = (sel == 0) ? 3 * CC : CC;

    const int tid = threadIdx.x;
    const int lane = tid & 31, wid = tid >> 5;
    const int wm = wid & 3, wn = wid >> 2;
    const int n0 = blockIdx.x * 128, m0 = blockIdx.y * 128;
    const int g = lane >> 2, j2 = (lane & 3) * 2;

    // ldmatrix per-lane byte offsets (row stride 80 B = 40 halves)
    const uint32_t aOffG =
        (uint32_t)(((((lane >> 3) & 1) * 8 + (lane & 7)) * 40 +
                    (lane >> 4) * 8) * 2);
    const uint32_t bOffG =
        (uint32_t)((((lane & 7) + ((lane >> 4) << 3)) * 40 +
                    ((lane >> 3) & 1) * 8) * 2);

    float acc[2][8][4];
#pragma unroll
    for (int mi = 0; mi < 2; mi++)
#pragma unroll
        for (int ni = 0; ni < 8; ni++)
#pragma unroll
            for (int r = 0; r < 4; r++) acc[mi][ni][r] = 0.f;

    const int nch = Kdim / 32;

#define ISSUE_LOADS(IT, STAGE) do {                                          \
        const int _k0 = (IT) * 32;                                          \
        __half* _sb = gsm + (STAGE) * GSTAGE;                               \
        _Pragma("unroll")                                                    \
        for (int _r = 0; _r < 2; _r++) {                                     \
            int _c = _r * 256 + tid;                                         \
            int _row = _c >> 2, _off = (_c & 3) * 8;                         \
            uint32_t _so = smem_u32(_sb + _row * 40 + _off);                 \
            size_t _ga = (size_t)(m0 + _row) * Kdim + _k0 + _off;            \
            size_t _gb = (size_t)(n0 + _row) * Kdim + _k0 + _off;            \
            cp16(_so,                 Ah + _ga);                             \
            cp16(_so + 2 * GOPE,      Al + _ga);                             \
            cp16(_so + 4 * GOPE,      Bh + _gb);                             \
            cp16(_so + 6 * GOPE,      Bl + _gb);                             \
        }                                                                    \
    } while (0)

    ISSUE_LOADS(0, 0);
    CP_COMMIT();

    for (int it = 0; it < nch; it++) {
        if (it + 1 < nch) {
            ISSUE_LOADS(it + 1, (it + 1) & 1);
            CP_COMMIT();
            CP_WAIT(1);
        } else {
            CP_WAIT(0);
        }
        __syncthreads();

        const uint32_t stage = smem_u32(gsm + (it & 1) * GSTAGE);
        const uint32_t sA = stage + aOffG + (uint32_t)(wm * 32 * 80);
        const uint32_t sB = stage + 2 * GOPE * 2 + bOffG +
                            (uint32_t)(wn * 64 * 80);

#pragma unroll
        for (int ks = 0; ks < 2; ks++) {
            uint32_t AH[2][4], AL[2][4];
#pragma unroll
            for (int mi = 0; mi < 2; mi++) {
                ldm_x4(AH[mi], sA + mi * 1280 + ks * 32);
                ldm_x4(AL[mi], sA + GOPE * 2 + mi * 1280 + ks * 32);
            }
#pragma unroll
            for (int np = 0; np < 4; np++) {
                uint32_t BH[4], BL[4];
                ldm_x4(BH, sB + np * 1280 + ks * 32);
                ldm_x4(BL, sB + GOPE * 2 + np * 1280 + ks * 32);
#pragma unroll
                for (int mi = 0; mi < 2; mi++) {
                    mma16816(acc[mi][2 * np],     AH[mi], &BH[0]);
                    mma16816(acc[mi][2 * np],     AH[mi], &BL[0]);
                    mma16816(acc[mi][2 * np],     AL[mi], &BH[0]);
                    mma16816(acc[mi][2 * np + 1], AH[mi], &BH[2]);
                    mma16816(acc[mi][2 * np + 1], AH[mi], &BL[2]);
                    mma16816(acc[mi][2 * np + 1], AL[mi], &BH[2]);
                }
            }
        }
        __syncthreads();
    }

#pragma unroll
    for (int mi = 0; mi < 2; mi++) {
#pragma unroll
        for (int ni = 0; ni < 8; ni++) {
            int m_r = m0 + wm * 32 + mi * 16 + g;
            int n_c = n0 + wn * 64 + ni * 8 + j2;
            float b0 = bias[n_c], b1 = bias[n_c + 1];
            float v00 = acc[mi][ni][0] + b0, v01 = acc[mi][ni][1] + b1;
            float v10 = acc[mi][ni][2] + b0, v11 = acc[mi][ni][3] + b1;
            if (sel == 1) {
                *(float2*)&Cout[(size_t)m_r * Ncols + n_c] = make_float2(v00, v01);
                *(float2*)&Cout[(size_t)(m_r + 8) * Ncols + n_c] = make_float2(v10, v11);
            } else {
                int part = n_c >> 10, rem = n_c & 1023;
                int hh = rem >> 6, dd = rem & 63;
                int b = m_r >> 11, t = m_r & 2047;
                int b2 = (m_r + 8) >> 11, t2 = (m_r + 8) & 2047;
                size_t o1 = (((size_t)b * HH + hh) * TT + t) * DD + dd;
                size_t o2 = (((size_t)b2 * HH + hh) * TT + t2) * DD + dd;
                if (part == 2) {
                    *(float2*)&g_v[o1] = make_float2(v00, v01);
                    *(float2*)&g_v[o2] = make_float2(v10, v11);
                } else {
                    __half* AHp = (part == 0) ? g_qh : g_kh;
                    __half* ALp = (part == 0) ? g_ql : g_kl;
                    __half h0, l0, h1, l1;
                    split2(v00, h0, l0);
                    split2(v01, h1, l1);
                    ((uint32_t*)AHp)[o1 >> 1] = pk(h0, h1);
                    ((uint32_t*)ALp)[o1 >> 1] = pk(l0, l1);
                    split2(v10, h0, l0);
                    split2(v11, h1, l1);
                    ((uint32_t*)AHp)[o2 >> 1] = pk(h0, h1);
                    ((uint32_t*)ALp)[o2 >> 1] = pk(l0, l1);
                }
            }
        }
    }
#undef ISSUE_LOADS
}

// ---------------------------------------------------------------------------
// Attention, recompute-QK variant with ldmatrix fragment loads.
// Pass 1: QK HMMA + fragment softmax reductions only -> m,l in registers.
// Pass 2: QK HMMA again (bit-identical), p = exp(s - m_fin)*inv_l, threshold
//         || regrow, split -> a_sm, AV HMMA.
// smem (110592 B, 2 blocks/SM):
//   stgK [0,36864) 2 stages | stgV [36864,73728) 2 stages |
//   q2 [73728,110592)  (pass 1)  ALIAS  a_h [73728,92160)+a_l [92160,110592)
// ---------------------------------------------------------------------------
#define ATTN_SMEM 110592

__global__ void __launch_bounds__(256, 2)
attn_kernel() {
    extern __shared__ char asmem[];
    __half* stgK = (__half*)asmem;                 // 2 x 18432 B
    __half* stgV = (__half*)(asmem + 36864);       // 2 x 18432 B
    __half* q_sm = (__half*)(asmem + 73728);       // 36864 B (pass 1)
    __half* a_smh = (__half*)(asmem + 73728);      // 18432 B (pass 2)
    __half* a_sml = (__half*)(asmem + 92160);      // 18432 B (pass 2)

    const int NQB = TT / 128;
    const int bh = blockIdx.z * HH + blockIdx.y;
    const int tid = threadIdx.x;
    const int lane = tid & 31, wid = tid >> 5;
    const int wm = wid & 3, wn = wid >> 2;
    const int g = lane >> 2, qd = lane & 3, j2 = qd * 2;

    // ldmatrix per-lane byte offsets (row stride 144 B = 72 halves)
    const uint32_t aOff =
        (uint32_t)(((((lane >> 3) & 1) * 8 + (lane & 7)) * 144) +
                   (lane >> 4) * 16);
    const uint32_t bOff =
        (uint32_t)((((lane & 7) + ((lane >> 4) << 3)) * 144) +
                   ((lane >> 3) & 1) * 16);

    const uint32_t* qh32 = (const uint32_t*)q_sm;
    const uint32_t* ql32 = qh32 + 4608;

    for (int half = 0; half < 2; half++) {
        const int qb = half == 0 ? (NQB - 1 - (int)blockIdx.x) : (int)blockIdx.x;
        const int t0 = qb * 128;
        const int ntiles = 2 * qb + 2;

        // ---- stage q2 via cp.async (2048 chunks, 8/thread) ----
#pragma unroll
        for (int rep = 0; rep < 8; rep++) {
            int c = rep * 256 + tid;
            int arr = c >> 10, cc = c & 1023, row = cc >> 3, j = cc & 7;
            const __half* src = (arr == 0 ? g_qh : g_ql) +
                ((size_t)bh * TT + t0 + row) * DD + j * 8;
            cp16(smem_u32(q_sm + arr * 9216 + row * 72 + j * 8), src);
        }
        CP_COMMIT();
        // ---- stage k2 tile 0 ----
#pragma unroll
        for (int rep = 0; rep < 4; rep++) {
            int c = rep * 256 + tid;
            int arr = c >> 9, cc = c & 511, row = cc >> 3, j = cc & 7;
            const __half* src = (arr == 0 ? g_kh : g_kl) +
                ((size_t)bh * TT + row) * DD + j * 8;
            cp16(smem_u32(stgK + arr * 4608 + row * 72 + j * 8), src);
        }
        CP_COMMIT();
        CP_WAIT(1);
        __syncthreads();

        // ---- Q fragments in registers (held across both passes) ----
        uint32_t qfh[4][4], qfl[4][4];
#pragma unroll
        for (int ks = 0; ks < 4; ks++) {
            int b0 = (16 * wid + g) * 36 + ks * 8 + qd;
            int b1 = b0 + 8 * 36;
            qfh[ks][0] = qh32[b0]; qfh[ks][1] = qh32[b1];
            qfh[ks][2] = qh32[b0 + 4]; qfh[ks][3] = qh32[b1 + 4];
            qfl[ks][0] = ql32[b0]; qfl[ks][1] = ql32[b1];
            qfl[ks][2] = ql32[b0 + 4]; qfl[ks][3] = ql32[b1 + 4];
        }

        const int r0 = 16 * wid + g, r1 = r0 + 8;
        const int tg0 = t0 + r0, tg1 = t0 + r1;
        float m0 = -1e30f, m1 = -1e30f, l0 = 0.f, l1 = 0.f;

        // ---------------- Pass 1: reductions only ----------------
        for (int it = 0; it < ntiles; it++) {
            const int s0 = it * 64;
            CP_WAIT(0);
            __syncthreads();
            if (it + 1 < ntiles) {
                __half* stn = stgK + ((it + 1) & 1) * 9216;
#pragma unroll
                for (int rep = 0; rep < 4; rep++) {
                    int c = rep * 256 + tid;
                    int arr = c >> 9, cc = c & 511, row = cc >> 3, j = cc & 7;
                    const __half* src = (arr == 0 ? g_kh : g_kl) +
                        ((size_t)bh * TT + s0 + 64 + row) * DD + j * 8;
                    cp16(smem_u32(stn + arr * 4608 + row * 72 + j * 8), src);
                }
                CP_COMMIT();
            }

            const uint32_t kbh = smem_u32(stgK + (it & 1) * 9216) + bOff;
            float acc[8][4];
#pragma unroll
            for (int ni = 0; ni < 8; ni++)
#pragma unroll
                for (int r = 0; r < 4; r++) acc[ni][r] = 0.f;
#pragma unroll
            for (int ks = 0; ks < 4; ks++) {
#pragma unroll
                for (int np = 0; np < 4; np++) {
                    uint32_t bhf[4], blf[4];
                    ldm_x4(bhf, kbh + np * 2304 + ks * 32);
                    ldm_x4(blf, kbh + 9216 + np * 2304 + ks * 32);
                    mma16816(acc[2 * np],     qfh[ks], &bhf[0]);
                    mma16816(acc[2 * np],     qfl[ks], &bhf[0]);
                    mma16816(acc[2 * np],     qfh[ks], &blf[0]);
                    mma16816(acc[2 * np + 1], qfh[ks], &bhf[2]);
                    mma16816(acc[2 * np + 1], qfl[ks], &bhf[2]);
                    mma16816(acc[2 * np + 1], qfh[ks], &blf[2]);
                }
            }

            float tm0 = -1e30f, tm1 = -1e30f;
#pragma unroll
            for (int ni = 0; ni < 8; ni++) {
                int s = s0 + ni * 8 + j2;
                acc[ni][0] = (s     <= tg0) ? acc[ni][0] * 0.125f : -1e30f;
                acc[ni][1] = (s + 1 <= tg0) ? acc[ni][1] * 0.125f : -1e30f;
                acc[ni][2] = (s     <= tg1) ? acc[ni][2] * 0.125f : -1e30f;
                acc[ni][3] = (s + 1 <= tg1) ? acc[ni][3] * 0.125f : -1e30f;
                tm0 = fmaxf(tm0, fmaxf(acc[ni][0], acc[ni][1]));
                tm1 = fmaxf(tm1, fmaxf(acc[ni][2], acc[ni][3]));
            }
            tm0 = fmaxf(tm0, __shfl_xor_sync(0xffffffffu, tm0, 1));
            tm0 = fmaxf(tm0, __shfl_xor_sync(0xffffffffu, tm0, 2));
            tm1 = fmaxf(tm1, __shfl_xor_sync(0xffffffffu, tm1, 1));
            tm1 = fmaxf(tm1, __shfl_xor_sync(0xffffffffu, tm1, 2));
            float mn0 = fmaxf(m0, tm0), mn1 = fmaxf(m1, tm1);
            float ls0 = 0.f, ls1 = 0.f;
#pragma unroll
            for (int ni = 0; ni < 8; ni++) {
                ls0 += __expf(acc[ni][0] - mn0) + __expf(acc[ni][1] - mn0);
                ls1 += __expf(acc[ni][2] - mn1) + __expf(acc[ni][3] - mn1);
            }
            ls0 += __shfl_xor_sync(0xffffffffu, ls0, 1);
            ls0 += __shfl_xor_sync(0xffffffffu, ls0, 2);
            ls1 += __shfl_xor_sync(0xffffffffu, ls1, 1);
            ls1 += __shfl_xor_sync(0xffffffffu, ls1, 2);
            l0 = l0 * __expf(m0 - mn0) + ls0; m0 = mn0;
            l1 = l1 * __expf(m1 - mn1) + ls1; m1 = mn1;
        }

        const float invl0 = 1.0f / l0, invl1 = 1.0f / l1;
        const size_t mrow0 = ((size_t)(bh * TT + tg0)) * (TT / 32);
        const size_t mrow1 = ((size_t)(bh * TT + tg1)) * (TT / 32);

        // ---- re-stage k0 + vt0 for pass 2 ----
        __syncthreads();
#pragma unroll
        for (int rep = 0; rep < 4; rep++) {
            int c = rep * 256 + tid;
            int arr = c >> 9, cc = c & 511, row = cc >> 3, j = cc & 7;
            const __half* srck = (arr == 0 ? g_kh : g_kl) +
                ((size_t)bh * TT + row) * DD + j * 8;
            cp16(smem_u32(stgK + arr * 4608 + row * 72 + j * 8), srck);
            const __half* srcv = (arr ? g_vtl : g_vth) +
                ((size_t)bh * DD + row) * TT + j * 8;
            cp16(smem_u32(stgV + arr * 4608 + row * 72 + j * 8), srcv);
        }
        CP_COMMIT();

        // ---------------- Pass 2: recompute, sparsify, AV ----------------
        float acc2[2][4][4];
#pragma unroll
        for (int mi = 0; mi < 2; mi++)
#pragma unroll
            for (int ni = 0; ni < 4; ni++)
#pragma unroll
                for (int r = 0; r < 4; r++) acc2[mi][ni][r] = 0.f;

        for (int it = 0; it < ntiles; it++) {
            const int s0 = it * 64;
            CP_WAIT(0);
            __syncthreads();
            if (it + 1 < ntiles) {
                __half* stnK = stgK + ((it + 1) & 1) * 9216;
                __half* stnV = stgV + ((it + 1) & 1) * 9216;
#pragma unroll
                for (int rep = 0; rep < 4; rep++) {
                    int c = rep * 256 + tid;
                    int arr = c >> 9, cc = c & 511, row = cc >> 3, j = cc & 7;
                    const __half* srck = (arr == 0 ? g_kh : g_kl) +
                        ((size_t)bh * TT + s0 + 64 + row) * DD + j * 8;
                    cp16(smem_u32(stnK + arr * 4608 + row * 72 + j * 8), srck);
                    const __half* srcv = (arr ? g_vtl : g_vth) +
                        ((size_t)bh * DD + row) * TT + s0 + 64 + j * 8;
                    cp16(smem_u32(stnV + arr * 4608 + row * 72 + j * 8), srcv);
                }
                CP_COMMIT();
            }

            // QK recompute (bit-identical to pass 1)
            const uint32_t kbh = smem_u32(stgK + (it & 1) * 9216) + bOff;
            float acc[8][4];
#pragma unroll
            for (int ni = 0; ni < 8; ni++)
#pragma unroll
                for (int r = 0; r < 4; r++) acc[ni][r] = 0.f;
#pragma unroll
            for (int ks = 0; ks < 4; ks++) {
#pragma unroll
                for (int np = 0; np < 4; np++) {
                    uint32_t bhf[4], blf[4];
                    ldm_x4(bhf, kbh + np * 2304 + ks * 32);
                    ldm_x4(blf, kbh + 9216 + np * 2304 + ks * 32);
                    mma16816(acc[2 * np],     qfh[ks], &bhf[0]);
                    mma16816(acc[2 * np],     qfl[ks], &bhf[0]);
                    mma16816(acc[2 * np],     qfh[ks], &blf[0]);
                    mma16816(acc[2 * np + 1], qfh[ks], &bhf[2]);
                    mma16816(acc[2 * np + 1], qfl[ks], &bhf[2]);
                    mma16816(acc[2 * np + 1], qfh[ks], &blf[2]);
                }
            }

            // p = exp(s - m_fin) * inv_l on fragments; threshold || regrow
            uint32_t w00 = g_mask[mrow0 + (s0 >> 5)];
            uint32_t w01 = g_mask[mrow0 + (s0 >> 5) + 1];
            uint32_t w10 = g_mask[mrow1 + (s0 >> 5)];
            uint32_t w11 = g_mask[mrow1 + (s0 >> 5) + 1];
#pragma unroll
            for (int ni = 0; ni < 8; ni++) {
                int s = s0 + ni * 8 + j2;
                int bp = (ni * 8 + j2) & 31;
                uint32_t wa = (ni < 4) ? w00 : w01;
                uint32_t wb = (ni < 4) ? w10 : w11;
                float s00 = (s     <= tg0) ? acc[ni][0] * 0.125f : -1e30f;
                float s01 = (s + 1 <= tg0) ? acc[ni][1] * 0.125f : -1e30f;
                float s10 = (s     <= tg1) ? acc[ni][2] * 0.125f : -1e30f;
                float s11 = (s + 1 <= tg1) ? acc[ni][3] * 0.125f : -1e30f;
                float p00 = __expf(s00 - m0) * invl0;
                float p01 = __expf(s01 - m0) * invl0;
                float p10 = __expf(s10 - m1) * invl1;
                float p11 = __expf(s11 - m1) * invl1;
                p00 = (p00 > 0.01f || ((wa >> (bp + 0)) & 1u)) ? p00 : 0.f;
                p01 = (p01 > 0.01f || ((wa >> (bp + 1)) & 1u)) ? p01 : 0.f;
                p10 = (p10 > 0.01f || ((wb >> (bp + 0)) & 1u)) ? p10 : 0.f;
                p11 = (p11 > 0.01f || ((wb >> (bp + 1)) & 1u)) ? p11 : 0.f;
                __half h0, lo0, h1, lo1;
                split2(p00, h0, lo0); split2(p01, h1, lo1);
                ((uint32_t*)a_smh)[r0 * 36 + ni * 4 + qd] = pk(h0, h1);
                ((uint32_t*)a_sml)[r0 * 36 + ni * 4 + qd] = pk(lo0, lo1);
                split2(p10, h0, lo0); split2(p11, h1, lo1);
                ((uint32_t*)a_smh)[r1 * 36 + ni * 4 + qd] = pk(h0, h1);
                ((uint32_t*)a_sml)[r1 * 36 + ni * 4 + qd] = pk(lo0, lo1);
            }
            __syncthreads();

            // AV MMA via ldmatrix
            const uint32_t aah = smem_u32(a_smh) + aOff +
                                 (uint32_t)(wm * 32 * 144);
            const uint32_t vvh = smem_u32(stgV + (it & 1) * 9216) + bOff +
                                 (uint32_t)(wn * 32 * 144);
#pragma unroll
            for (int ks = 0; ks < 4; ks++) {
                uint32_t AH[2][4], AL[2][4];
#pragma unroll
                for (int mi = 0; mi < 2; mi++) {
                    ldm_x4(AH[mi], aah + mi * 2304 + ks * 32);
                    ldm_x4(AL[mi], aah + 18432 + mi * 2304 + ks * 32);
                }
#pragma unroll
                for (int np = 0; np < 2; np++) {
                    uint32_t VH[4], VL[4];
                    ldm_x4(VH, vvh + np * 2304 + ks * 32);
                    ldm_x4(VL, vvh + 9216 + np * 2304 + ks * 32);
#pragma unroll
                    for (int mi = 0; mi < 2; mi++) {
                        mma16816(acc2[mi][2 * np],     AH[mi], &VH[0]);
                        mma16816(acc2[mi][2 * np],     AH[mi], &VL[0]);
                        mma16816(acc2[mi][2 * np],     AL[mi], &VH[0]);
                        mma16816(acc2[mi][2 * np + 1], AH[mi], &VH[2]);
                        mma16816(acc2[mi][2 * np + 1], AH[mi], &VL[2]);
                        mma16816(acc2[mi][2 * np + 1], AL[mi], &VH[2]);
                    }
                }
            }
        }

        // epilogue: split output, write g_aoh/g_aol directly
        const int b = blockIdx.z, h = blockIdx.y;
#pragma unroll
        for (int mi = 0; mi < 2; mi++) {
#pragma unroll
            for (int ni = 0; ni < 4; ni++) {
                int mrow = wm * 32 + mi * 16 + g;
                int n = wn * 32 + ni * 8 + j2;
#pragma unroll
                for (int rr = 0; rr < 2; rr++) {
                    int t = t0 + mrow + rr * 8;
                    float v0 = acc2[mi][ni][rr * 2 + 0];
                    float v1 = acc2[mi][ni][rr * 2 + 1];
                    __half h0, lo0, h1, lo1;
                    split2(v0, h0, lo0);
                    split2(v1, h1, lo1);
                    size_t o = ((size_t)(b * TT + t) * CC + h * 64 + n) >> 1;
                    ((uint32_t*)g_aoh)[o] = pk(h0, h1);
                    ((uint32_t*)g_aol)[o] = pk(lo0, lo1);
                }
            }
        }
        __syncthreads();
    }
}

// ---------------------------------------------------------------------------
extern "C" void kernel_launch(void* const* d_in, const int* in_sizes, int n_in,
                              void* d_out, int out_size) {
    const float* x    = (const float*)d_in[0];
    const float* Wqkv = (const float*)d_in[1];
    const float* bqkv = (const float*)d_in[2];
    const float* Wout = (const float*)d_in[3];
    const float* bout = (const float*)d_in[4];
    float* out = (float*)d_out;

    cudaFuncSetAttribute(attn_kernel,
                         cudaFuncAttributeMaxDynamicSharedMemorySize, ATTN_SMEM);
    cudaFuncSetAttribute(hmma_gemm,
                         cudaFuncAttributeMaxDynamicSharedMemorySize, GEMM_SMEM);

    // 0) Regrow bitmask (input-independent, standalone)
    mask_kernel<<<dim3(4, TT, BB * HH), 256>>>();

    // 1) Split-f16 conversions
    conv_rows<<<(BB * TT * CC / 4 + 255) / 256, 256>>>(x, BB * TT * CC / 4);
    conv_tr<<<dim3(3 * CC / 32, CC / 32), dim3(32, 8)>>>(Wqkv, CC, 3 * CC, 0);
    conv_tr<<<dim3(CC / 32, CC / 32), dim3(32, 8)>>>(Wout, CC, CC, 1);

    // 2) QKV projection -> q,k (2-way f16), v (fp32)
    hmma_gemm<<<dim3(3 * CC / 128, BB * TT / 128), 256, GEMM_SMEM>>>(
        bqkv, nullptr, 0);

    // 2b) V -> V^T f16 hi/lo
    vt_split<<<dim3(DD / 32, TT / 32, BB * HH), dim3(32, 8)>>>();

    // 3) Attention (recompute-QK, ldmatrix fragment loads)
    attn_kernel<<<dim3(TT / 256, HH, BB), 256, ATTN_SMEM>>>();

    // 4) Output projection
    hmma_gemm<<<dim3(CC / 128, BB * TT / 128), 256, GEMM_SMEM>>>(
        bout, out, 1);
}

// round 17
// speedup vs baseline: 1.1136x; 1.0065x over previous
#include <cuda_runtime.h>
#include <cuda_fp16.h>
#include <stdint.h>

#define BB 2
#define TT 2048
#define CC 1024
#define HH 16
#define DD 64

// ---------------------------------------------------------------------------
// Scratch (allocation-free rule: __device__ globals). Device-code refs only.
// ---------------------------------------------------------------------------
__device__ float g_v[BB * HH * TT * DD];
__device__ uint32_t g_mask[(size_t)BB * HH * TT * (TT / 32)];
// q, k in 2-way f16 decomposition (h + l ~ fp32): [bh][t][d]
__device__ __half g_qh[BB * HH * TT * DD], g_ql[BB * HH * TT * DD];
__device__ __half g_kh[BB * HH * TT * DD], g_kl[BB * HH * TT * DD];
// split-f16 GEMM operands
__device__ __half g_xh[BB * TT * CC], g_xl[BB * TT * CC];
__device__ __half g_wqh[3 * CC * CC], g_wql[3 * CC * CC];
__device__ __half g_woh[CC * CC], g_wol[CC * CC];
__device__ __half g_aoh[BB * TT * CC], g_aol[BB * TT * CC];
// V transposed per (b,h): [bh][d][t], f16 hi/lo
__device__ __half g_vth[(size_t)BB * HH * DD * TT];
__device__ __half g_vtl[(size_t)BB * HH * DD * TT];

// ---------------------------------------------------------------------------
// sm_80-level PTX helpers
// ---------------------------------------------------------------------------
__device__ __forceinline__ uint32_t smem_u32(const void* p) {
    uint32_t a;
    asm("{ .reg .u64 t; cvta.to.shared.u64 t, %1; cvt.u32.u64 %0, t; }"
        : "=r"(a) : "l"(p));
    return a;
}
__device__ __forceinline__ void cp16(uint32_t dst, const void* src) {
    asm volatile("cp.async.cg.shared.global [%0], [%1], 16;"
                 :: "r"(dst), "l"(src) : "memory");
}
#define CP_COMMIT() asm volatile("cp.async.commit_group;" ::: "memory")
#define CP_WAIT(n)  asm volatile("cp.async.wait_group %0;" :: "n"(n) : "memory")

// f16 x f16 -> f32 accumulate MMA
__device__ __forceinline__ void mma16816(float* c, const uint32_t* a,
                                         const uint32_t* b) {
    asm volatile(
        "mma.sync.aligned.m16n8k16.row.col.f32.f16.f16.f32 "
        "{%0,%1,%2,%3},{%4,%5,%6,%7},{%8,%9},{%0,%1,%2,%3};"
        : "+f"(c[0]), "+f"(c[1]), "+f"(c[2]), "+f"(c[3])
        : "r"(a[0]), "r"(a[1]), "r"(a[2]), "r"(a[3]), "r"(b[0]), "r"(b[1]));
}
// ldmatrix x4: loads 4 8x8 b16 tiles; lane L holds (row L>>2, col 2(L&3)).
__device__ __forceinline__ void ldm_x4(uint32_t* r, uint32_t addr) {
    asm volatile(
        "ldmatrix.sync.aligned.m8n8.x4.shared.b16 {%0,%1,%2,%3}, [%4];"
        : "=r"(r[0]), "=r"(r[1]), "=r"(r[2]), "=r"(r[3]) : "r"(addr));
}
__device__ __forceinline__ uint32_t pk(__half a, __half b) {
    return (uint32_t)__half_as_ushort(a) |
           ((uint32_t)__half_as_ushort(b) << 16);
}
__device__ __forceinline__ void split2(float v, __half& h, __half& l) {
    h = __float2half_rn(v);
    l = __float2half_rn(v - __half2float(h));
}

// ---------------------------------------------------------------------------
// Threefry-2x32, key = (0, 42)
// ---------------------------------------------------------------------------
__device__ __forceinline__ uint2 threefry_0_42(uint32_t x0, uint32_t x1) {
    const uint32_t ks0 = 0u, ks1 = 42u;
    const uint32_t ks2 = 0x1BD11BDAu ^ ks0 ^ ks1;
    x0 += ks0; x1 += ks1;
#define TF_RND(rot) { x0 += x1; x1 = __funnelshift_l(x1, x1, (rot)); x1 ^= x0; }
    TF_RND(13) TF_RND(15) TF_RND(26) TF_RND(6)
    x0 += ks1; x1 += ks2 + 1u;
    TF_RND(17) TF_RND(29) TF_RND(16) TF_RND(24)
    x0 += ks2; x1 += ks0 + 2u;
    TF_RND(13) TF_RND(15) TF_RND(26) TF_RND(6)
    x0 += ks0; x1 += ks1 + 3u;
    TF_RND(17) TF_RND(29) TF_RND(16) TF_RND(24)
    x0 += ks1; x1 += ks2 + 4u;
    TF_RND(13) TF_RND(15) TF_RND(26) TF_RND(6)
    x0 += ks2; x1 += ks0 + 5u;
#undef TF_RND
    return make_uint2(x0, x1);
}
__device__ __forceinline__ bool regrow_test(uint32_t idx) {
    uint2 rb = threefry_0_42(0u, idx);
    return ((rb.x ^ rb.y) >> 9) <= 419430u;
}

// Standalone mask kernel (two independent threefry chains per thread, ILP 2).
__global__ void __launch_bounds__(256)
mask_kernel() {
    const int t  = blockIdx.y;
    const int bh = blockIdx.z;
    const int wid = threadIdx.x >> 5, lane = threadIdx.x & 31;
    const int w0 = (blockIdx.x * 8 + wid) * 2;
    if (w0 * 32 > t) return;
    const uint32_t base = ((uint32_t)(bh * TT + t)) * (uint32_t)TT;
    bool r0 = regrow_test(base + (uint32_t)(w0 * 32 + lane));
    bool r1 = regrow_test(base + (uint32_t)(w0 * 32 + 32 + lane));
    uint32_t b0 = __ballot_sync(0xffffffffu, r0);
    uint32_t b1 = __ballot_sync(0xffffffffu, r1);
    if (lane == 0) {
        size_t o = ((size_t)(bh * TT + t)) * (TT / 32) + w0;
        g_mask[o] = b0;
        if ((w0 + 1) * 32 <= t) g_mask[o + 1] = b1;
    }
}

// ---------------------------------------------------------------------------
// fp32 -> f16 hi/lo split: x -> g_xh/g_xl
// ---------------------------------------------------------------------------
__global__ void __launch_bounds__(256)
conv_rows(const float* __restrict__ X, int n4) {
    int i = blockIdx.x * 256 + threadIdx.x;
    if (i >= n4) return;
    float4 v = ((const float4*)X)[i];
    float vv[4] = {v.x, v.y, v.z, v.w};
    __half h[4], l[4];
#pragma unroll
    for (int j = 0; j < 4; j++) split2(vv[j], h[j], l[j]);
    ((uint32_t*)g_xh)[i * 2]     = pk(h[0], h[1]);
    ((uint32_t*)g_xh)[i * 2 + 1] = pk(h[2], h[3]);
    ((uint32_t*)g_xl)[i * 2]     = pk(l[0], l[1]);
    ((uint32_t*)g_xl)[i * 2 + 1] = pk(l[2], l[3]);
}

// W [K][N] fp32 -> W^T [N][K] f16 hi/lo.  sel 0: g_wqh/g_wql, 1: g_woh/g_wol
__global__ void __launch_bounds__(256)
conv_tr(const float* __restrict__ W, int K, int N, int sel) {
    __shared__ float sm[32][33];
    __half* Th = (sel == 0) ? g_wqh : g_woh;
    __half* Tl = (sel == 0) ? g_wql : g_wol;
    const int n0 = blockIdx.x * 32, k0 = blockIdx.y * 32;
    const int tx = threadIdx.x, ty = threadIdx.y;
#pragma unroll
    for (int i = 0; i < 4; i++)
        sm[ty + i * 8][tx] = W[(size_t)(k0 + ty + i * 8) * N + n0 + tx];
    __syncthreads();
#pragma unroll
    for (int i = 0; i < 4; i++) {
        float v = sm[tx][ty + i * 8];
        __half h, l;
        split2(v, h, l);
        size_t o = (size_t)(n0 + ty + i * 8) * K + k0 + tx;
        Th[o] = h; Tl[o] = l;
    }
}

// g_v [bh][t][d] fp32 -> g_vth/g_vtl [bh][d][t] f16 hi/lo
__global__ void __launch_bounds__(256)
vt_split() {
    __shared__ float sm[32][33];
    const int bh = blockIdx.z;
    const int d0 = blockIdx.x * 32;
    const int t0 = blockIdx.y * 32;
    const int tx = threadIdx.x, ty = threadIdx.y;
    const float* src = g_v + (size_t)bh * TT * DD;
#pragma unroll
    for (int i = 0; i < 4; i++)
        sm[ty + i * 8][tx] = src[(size_t)(t0 + ty + i * 8) * DD + d0 + tx];
    __syncthreads();
#pragma unroll
    for (int i = 0; i < 4; i++) {
        float v = sm[tx][ty + i * 8];
        __half h, l;
        split2(v, h, l);
        size_t o = ((size_t)bh * DD + d0 + ty + i * 8) * TT + t0 + tx;
        g_vth[o] = h; g_vtl[o] = l;
    }
}

// ---------------------------------------------------------------------------
// Split-f16 HMMA GEMM with ldmatrix fragment loads: C = A @ Bt^T + bias.
//   sel 0: A=g_xh/g_xl, Bt=g_wqh/g_wql; scatter q,k as 2-way f16, v fp32.
//   sel 1: A=g_aoh/g_aol, Bt=g_woh/g_wol; row-major store to Cout.
// ---------------------------------------------------------------------------
#define GOPE   (128 * 40)
#define GSTAGE (4 * GOPE)
#define GEMM_SMEM (2 * GSTAGE * 2)

__global__ void __launch_bounds__(256)
hmma_gemm(const float* __restrict__ bias, float* __restrict__ Cout, int sel) {
    extern __shared__ __half gsm[];
    const __half* Ah = (sel == 0) ? g_xh : g_aoh;
    const __half* Al = (sel == 0) ? g_xl : g_aol;
    const __half* Bh = (sel == 0) ? g_wqh : g_woh;
    const __half* Bl = (sel == 0) ? g_wql : g_wol;
    const int Kdim = CC;
    const int Ncols = (sel == 0) ? 3 * CC : CC;

    const int tid = threadIdx.x;
    const int lane = tid & 31, wid = tid >> 5;
    const int wm = wid & 3, wn = wid >> 2;
    const int n0 = blockIdx.x * 128, m0 = blockIdx.y * 128;
    const int g = lane >> 2, j2 = (lane & 3) * 2;

    const uint32_t aOffG =
        (uint32_t)(((((lane >> 3) & 1) * 8 + (lane & 7)) * 40 +
                    (lane >> 4) * 8) * 2);
    const uint32_t bOffG =
        (uint32_t)((((lane & 7) + ((lane >> 4) << 3)) * 40 +
                    ((lane >> 3) & 1) * 8) * 2);

    float acc[2][8][4];
#pragma unroll
    for (int mi = 0; mi < 2; mi++)
#pragma unroll
        for (int ni = 0; ni < 8; ni++)
#pragma unroll
            for (int r = 0; r < 4; r++) acc[mi][ni][r] = 0.f;

    const int nch = Kdim / 32;

#define ISSUE_LOADS(IT, STAGE) do {                                          \
        const int _k0 = (IT) * 32;                                          \
        __half* _sb = gsm + (STAGE) * GSTAGE;                               \
        _Pragma("unroll")                                                    \
        for (int _r = 0; _r < 2; _r++) {                                     \
            int _c = _r * 256 + tid;                                         \
            int _row = _c >> 2, _off = (_c & 3) * 8;                         \
            uint32_t _so = smem_u32(_sb + _row * 40 + _off);                 \
            size_t _ga = (size_t)(m0 + _row) * Kdim + _k0 + _off;            \
            size_t _gb = (size_t)(n0 + _row) * Kdim + _k0 + _off;            \
            cp16(_so,                 Ah + _ga);                             \
            cp16(_so + 2 * GOPE,      Al + _ga);                             \
            cp16(_so + 4 * GOPE,      Bh + _gb);                             \
            cp16(_so + 6 * GOPE,      Bl + _gb);                             \
        }                                                                    \
    } while (0)

    ISSUE_LOADS(0, 0);
    CP_COMMIT();

    for (int it = 0; it < nch; it++) {
        if (it + 1 < nch) {
            ISSUE_LOADS(it + 1, (it + 1) & 1);
            CP_COMMIT();
            CP_WAIT(1);
        } else {
            CP_WAIT(0);
        }
        __syncthreads();

        const uint32_t stage = smem_u32(gsm + (it & 1) * GSTAGE);
        const uint32_t sA = stage + aOffG + (uint32_t)(wm * 32 * 80);
        const uint32_t sB = stage + 2 * GOPE * 2 + bOffG +
                            (uint32_t)(wn * 64 * 80);

#pragma unroll
        for (int ks = 0; ks < 2; ks++) {
            uint32_t AH[2][4], AL[2][4];
#pragma unroll
            for (int mi = 0; mi < 2; mi++) {
                ldm_x4(AH[mi], sA + mi * 1280 + ks * 32);
                ldm_x4(AL[mi], sA + GOPE * 2 + mi * 1280 + ks * 32);
            }
#pragma unroll
            for (int np = 0; np < 4; np++) {
                uint32_t BH[4], BL[4];
                ldm_x4(BH, sB + np * 1280 + ks * 32);
                ldm_x4(BL, sB + GOPE * 2 + np * 1280 + ks * 32);
#pragma unroll
                for (int mi = 0; mi < 2; mi++) {
                    mma16816(acc[mi][2 * np],     AH[mi], &BH[0]);
                    mma16816(acc[mi][2 * np],     AH[mi], &BL[0]);
                    mma16816(acc[mi][2 * np],     AL[mi], &BH[0]);
                    mma16816(acc[mi][2 * np + 1], AH[mi], &BH[2]);
                    mma16816(acc[mi][2 * np + 1], AH[mi], &BL[2]);
                    mma16816(acc[mi][2 * np + 1], AL[mi], &BH[2]);
                }
            }
        }
        __syncthreads();
    }

#pragma unroll
    for (int mi = 0; mi < 2; mi++) {
#pragma unroll
        for (int ni = 0; ni < 8; ni++) {
            int m_r = m0 + wm * 32 + mi * 16 + g;
            int n_c = n0 + wn * 64 + ni * 8 + j2;
            float b0 = bias[n_c], b1 = bias[n_c + 1];
            float v00 = acc[mi][ni][0] + b0, v01 = acc[mi][ni][1] + b1;
            float v10 = acc[mi][ni][2] + b0, v11 = acc[mi][ni][3] + b1;
            if (sel == 1) {
                *(float2*)&Cout[(size_t)m_r * Ncols + n_c] = make_float2(v00, v01);
                *(float2*)&Cout[(size_t)(m_r + 8) * Ncols + n_c] = make_float2(v10, v11);
            } else {
                int part = n_c >> 10, rem = n_c & 1023;
                int hh = rem >> 6, dd = rem & 63;
                int b = m_r >> 11, t = m_r & 2047;
                int b2 = (m_r + 8) >> 11, t2 = (m_r + 8) & 2047;
                size_t o1 = (((size_t)b * HH + hh) * TT + t) * DD + dd;
                size_t o2 = (((size_t)b2 * HH + hh) * TT + t2) * DD + dd;
                if (part == 2) {
                    *(float2*)&g_v[o1] = make_float2(v00, v01);
                    *(float2*)&g_v[o2] = make_float2(v10, v11);
                } else {
                    __half* AHp = (part == 0) ? g_qh : g_kh;
                    __half* ALp = (part == 0) ? g_ql : g_kl;
                    __half h0, l0, h1, l1;
                    split2(v00, h0, l0);
                    split2(v01, h1, l1);
                    ((uint32_t*)AHp)[o1 >> 1] = pk(h0, h1);
                    ((uint32_t*)ALp)[o1 >> 1] = pk(l0, l1);
                    split2(v10, h0, l0);
                    split2(v11, h1, l1);
                    ((uint32_t*)AHp)[o2 >> 1] = pk(h0, h1);
                    ((uint32_t*)ALp)[o2 >> 1] = pk(l0, l1);
                }
            }
        }
    }
#undef ISSUE_LOADS
}

// ---------------------------------------------------------------------------
// Attention, recompute-QK + register-P AV (FlashAttention-style fragment
// reuse): the QK C-fragments become AV A-fragments in-register, eliminating
// the a_sm round-trip and one sync per pass-2 iteration. Warp AV tile is
// 16m x 64n (same 16-row strip the warp owns in QK).
// smem (110592 B, 2 blocks/SM):
//   stgK [0,36864) 2 stages | stgV [36864,73728) 2 stages |
//   q2 [73728,110592) (pass 1 only)
// ---------------------------------------------------------------------------
#define ATTN_SMEM 110592

__global__ void __launch_bounds__(256, 2)
attn_kernel() {
    extern __shared__ char asmem[];
    __half* stgK = (__half*)asmem;                 // 2 x 18432 B
    __half* stgV = (__half*)(asmem + 36864);       // 2 x 18432 B
    __half* q_sm = (__half*)(asmem + 73728);       // 36864 B (pass 1)

    const int NQB = TT / 128;
    const int bh = blockIdx.z * HH + blockIdx.y;
    const int tid = threadIdx.x;
    const int lane = tid & 31, wid = tid >> 5;
    const int g = lane >> 2, qd = lane & 3, j2 = qd * 2;

    // ldmatrix per-lane byte offsets (row stride 144 B = 72 halves)
    const uint32_t bOff =
        (uint32_t)((((lane & 7) + ((lane >> 4) << 3)) * 144) +
                   ((lane >> 3) & 1) * 16);

    const uint32_t* qh32 = (const uint32_t*)q_sm;
    const uint32_t* ql32 = qh32 + 4608;

    for (int half = 0; half < 2; half++) {
        const int qb = half == 0 ? (NQB - 1 - (int)blockIdx.x) : (int)blockIdx.x;
        const int t0 = qb * 128;
        const int ntiles = 2 * qb + 2;

        // ---- stage q2 via cp.async (2048 chunks, 8/thread) ----
#pragma unroll
        for (int rep = 0; rep < 8; rep++) {
            int c = rep * 256 + tid;
            int arr = c >> 10, cc = c & 1023, row = cc >> 3, j = cc & 7;
            const __half* src = (arr == 0 ? g_qh : g_ql) +
                ((size_t)bh * TT + t0 + row) * DD + j * 8;
            cp16(smem_u32(q_sm + arr * 9216 + row * 72 + j * 8), src);
        }
        CP_COMMIT();
        // ---- stage k2 tile 0 ----
#pragma unroll
        for (int rep = 0; rep < 4; rep++) {
            int c = rep * 256 + tid;
            int arr = c >> 9, cc = c & 511, row = cc >> 3, j = cc & 7;
            const __half* src = (arr == 0 ? g_kh : g_kl) +
                ((size_t)bh * TT + row) * DD + j * 8;
            cp16(smem_u32(stgK + arr * 4608 + row * 72 + j * 8), src);
        }
        CP_COMMIT();
        CP_WAIT(1);
        __syncthreads();

        // ---- Q fragments in registers (held across both passes) ----
        uint32_t qfh[4][4], qfl[4][4];
#pragma unroll
        for (int ks = 0; ks < 4; ks++) {
            int b0 = (16 * wid + g) * 36 + ks * 8 + qd;
            int b1 = b0 + 8 * 36;
            qfh[ks][0] = qh32[b0]; qfh[ks][1] = qh32[b1];
            qfh[ks][2] = qh32[b0 + 4]; qfh[ks][3] = qh32[b1 + 4];
            qfl[ks][0] = ql32[b0]; qfl[ks][1] = ql32[b1];
            qfl[ks][2] = ql32[b0 + 4]; qfl[ks][3] = ql32[b1 + 4];
        }

        const int r0 = 16 * wid + g, r1 = r0 + 8;
        const int tg0 = t0 + r0, tg1 = t0 + r1;
        float m0 = -1e30f, m1 = -1e30f, l0 = 0.f, l1 = 0.f;

        // ---------------- Pass 1: reductions only ----------------
        for (int it = 0; it < ntiles; it++) {
            const int s0 = it * 64;
            CP_WAIT(0);
            __syncthreads();
            if (it + 1 < ntiles) {
                __half* stn = stgK + ((it + 1) & 1) * 9216;
#pragma unroll
                for (int rep = 0; rep < 4; rep++) {
                    int c = rep * 256 + tid;
                    int arr = c >> 9, cc = c & 511, row = cc >> 3, j = cc & 7;
                    const __half* src = (arr == 0 ? g_kh : g_kl) +
                        ((size_t)bh * TT + s0 + 64 + row) * DD + j * 8;
                    cp16(smem_u32(stn + arr * 4608 + row * 72 + j * 8), src);
                }
                CP_COMMIT();
            }

            const uint32_t kbh = smem_u32(stgK + (it & 1) * 9216) + bOff;
            float acc[8][4];
#pragma unroll
            for (int ni = 0; ni < 8; ni++)
#pragma unroll
                for (int r = 0; r < 4; r++) acc[ni][r] = 0.f;
#pragma unroll
            for (int ks = 0; ks < 4; ks++) {
#pragma unroll
                for (int np = 0; np < 4; np++) {
                    uint32_t bhf[4], blf[4];
                    ldm_x4(bhf, kbh + np * 2304 + ks * 32);
                    ldm_x4(blf, kbh + 9216 + np * 2304 + ks * 32);
                    mma16816(acc[2 * np],     qfh[ks], &bhf[0]);
                    mma16816(acc[2 * np],     qfl[ks], &bhf[0]);
                    mma16816(acc[2 * np],     qfh[ks], &blf[0]);
                    mma16816(acc[2 * np + 1], qfh[ks], &bhf[2]);
                    mma16816(acc[2 * np + 1], qfl[ks], &bhf[2]);
                    mma16816(acc[2 * np + 1], qfh[ks], &blf[2]);
                }
            }

            const bool fullt = (it < 2 * qb);
            float tm0 = -1e30f, tm1 = -1e30f;
            if (fullt) {
#pragma unroll
                for (int ni = 0; ni < 8; ni++) {
                    acc[ni][0] *= 0.125f; acc[ni][1] *= 0.125f;
                    acc[ni][2] *= 0.125f; acc[ni][3] *= 0.125f;
                    tm0 = fmaxf(tm0, fmaxf(acc[ni][0], acc[ni][1]));
                    tm1 = fmaxf(tm1, fmaxf(acc[ni][2], acc[ni][3]));
                }
            } else {
#pragma unroll
                for (int ni = 0; ni < 8; ni++) {
                    int s = s0 + ni * 8 + j2;
                    acc[ni][0] = (s     <= tg0) ? acc[ni][0] * 0.125f : -1e30f;
                    acc[ni][1] = (s + 1 <= tg0) ? acc[ni][1] * 0.125f : -1e30f;
                    acc[ni][2] = (s     <= tg1) ? acc[ni][2] * 0.125f : -1e30f;
                    acc[ni][3] = (s + 1 <= tg1) ? acc[ni][3] * 0.125f : -1e30f;
                    tm0 = fmaxf(tm0, fmaxf(acc[ni][0], acc[ni][1]));
                    tm1 = fmaxf(tm1, fmaxf(acc[ni][2], acc[ni][3]));
                }
            }
            tm0 = fmaxf(tm0, __shfl_xor_sync(0xffffffffu, tm0, 1));
            tm0 = fmaxf(tm0, __shfl_xor_sync(0xffffffffu, tm0, 2));
            tm1 = fmaxf(tm1, __shfl_xor_sync(0xffffffffu, tm1, 1));
            tm1 = fmaxf(tm1, __shfl_xor_sync(0xffffffffu, tm1, 2));
            float mn0 = fmaxf(m0, tm0), mn1 = fmaxf(m1, tm1);
            float ls0 = 0.f, ls1 = 0.f;
#pragma unroll
            for (int ni = 0; ni < 8; ni++) {
                ls0 += __expf(acc[ni][0] - mn0) + __expf(acc[ni][1] - mn0);
                ls1 += __expf(acc[ni][2] - mn1) + __expf(acc[ni][3] - mn1);
            }
            ls0 += __shfl_xor_sync(0xffffffffu, ls0, 1);
            ls0 += __shfl_xor_sync(0xffffffffu, ls0, 2);
            ls1 += __shfl_xor_sync(0xffffffffu, ls1, 1);
            ls1 += __shfl_xor_sync(0xffffffffu, ls1, 2);
            l0 = l0 * __expf(m0 - mn0) + ls0; m0 = mn0;
            l1 = l1 * __expf(m1 - mn1) + ls1; m1 = mn1;
        }

        const float invl0 = 1.0f / l0, invl1 = 1.0f / l1;
        const size_t mrow0 = ((size_t)(bh * TT + tg0)) * (TT / 32);
        const size_t mrow1 = ((size_t)(bh * TT + tg1)) * (TT / 32);

        // ---- re-stage k0 + vt0 for pass 2 ----
        __syncthreads();
#pragma unroll
        for (int rep = 0; rep < 4; rep++) {
            int c = rep * 256 + tid;
            int arr = c >> 9, cc = c & 511, row = cc >> 3, j = cc & 7;
            const __half* srck = (arr == 0 ? g_kh : g_kl) +
                ((size_t)bh * TT + row) * DD + j * 8;
            cp16(smem_u32(stgK + arr * 4608 + row * 72 + j * 8), srck);
            const __half* srcv = (arr ? g_vtl : g_vth) +
                ((size_t)bh * DD + row) * TT + j * 8;
            cp16(smem_u32(stgV + arr * 4608 + row * 72 + j * 8), srcv);
        }
        CP_COMMIT();

        // ---------------- Pass 2: recompute, sparsify, AV ----------------
        float acc2[8][4];
#pragma unroll
        for (int ni = 0; ni < 8; ni++)
#pragma unroll
            for (int r = 0; r < 4; r++) acc2[ni][r] = 0.f;

        for (int it = 0; it < ntiles; it++) {
            const int s0 = it * 64;
            CP_WAIT(0);
            __syncthreads();
            if (it + 1 < ntiles) {
                __half* stnK = stgK + ((it + 1) & 1) * 9216;
                __half* stnV = stgV + ((it + 1) & 1) * 9216;
#pragma unroll
                for (int rep = 0; rep < 4; rep++) {
                    int c = rep * 256 + tid;
                    int arr = c >> 9, cc = c & 511, row = cc >> 3, j = cc & 7;
                    const __half* srck = (arr == 0 ? g_kh : g_kl) +
                        ((size_t)bh * TT + s0 + 64 + row) * DD + j * 8;
                    cp16(smem_u32(stnK + arr * 4608 + row * 72 + j * 8), srck);
                    const __half* srcv = (arr ? g_vtl : g_vth) +
                        ((size_t)bh * DD + row) * TT + s0 + 64 + j * 8;
                    cp16(smem_u32(stnV + arr * 4608 + row * 72 + j * 8), srcv);
                }
                CP_COMMIT();
            }

            // QK recompute (bit-identical to pass 1)
            const uint32_t kbh = smem_u32(stgK + (it & 1) * 9216) + bOff;
            float acc[8][4];
#pragma unroll
            for (int ni = 0; ni < 8; ni++)
#pragma unroll
                for (int r = 0; r < 4; r++) acc[ni][r] = 0.f;
#pragma unroll
            for (int ks = 0; ks < 4; ks++) {
#pragma unroll
                for (int np = 0; np < 4; np++) {
                    uint32_t bhf[4], blf[4];
                    ldm_x4(bhf, kbh + np * 2304 + ks * 32);
                    ldm_x4(blf, kbh + 9216 + np * 2304 + ks * 32);
                    mma16816(acc[2 * np],     qfh[ks], &bhf[0]);
                    mma16816(acc[2 * np],     qfl[ks], &bhf[0]);
                    mma16816(acc[2 * np],     qfh[ks], &blf[0]);
                    mma16816(acc[2 * np + 1], qfh[ks], &bhf[2]);
                    mma16816(acc[2 * np + 1], qfl[ks], &bhf[2]);
                    mma16816(acc[2 * np + 1], qfh[ks], &blf[2]);
                }
            }

            const bool fullt = (it < 2 * qb);
            uint32_t w00 = g_mask[mrow0 + (s0 >> 5)];
            uint32_t w01 = g_mask[mrow0 + (s0 >> 5) + 1];
            uint32_t w10 = g_mask[mrow1 + (s0 >> 5)];
            uint32_t w11 = g_mask[mrow1 + (s0 >> 5) + 1];
            const uint32_t vvh = smem_u32(stgV + (it & 1) * 9216) + bOff;

            // Fused sparsify + AV, one ks (= 2 S n-tiles) at a time:
            // QK C-fragments become AV A-fragments in-register.
#pragma unroll
            for (int ks = 0; ks < 4; ks++) {
                uint32_t afh[4], afl[4];
#pragma unroll
                for (int h2 = 0; h2 < 2; h2++) {
                    const int ni = 2 * ks + h2;
                    int bp = (ni * 8 + j2) & 31;
                    uint32_t wa = (ni < 4) ? w00 : w01;
                    uint32_t wb = (ni < 4) ? w10 : w11;
                    float s00, s01, s10, s11;
                    if (fullt) {
                        s00 = acc[ni][0] * 0.125f; s01 = acc[ni][1] * 0.125f;
                        s10 = acc[ni][2] * 0.125f; s11 = acc[ni][3] * 0.125f;
                    } else {
                        int s = s0 + ni * 8 + j2;
                        s00 = (s     <= tg0) ? acc[ni][0] * 0.125f : -1e30f;
                        s01 = (s + 1 <= tg0) ? acc[ni][1] * 0.125f : -1e30f;
                        s10 = (s     <= tg1) ? acc[ni][2] * 0.125f : -1e30f;
                        s11 = (s + 1 <= tg1) ? acc[ni][3] * 0.125f : -1e30f;
                    }
                    float p00 = __expf(s00 - m0) * invl0;
                    float p01 = __expf(s01 - m0) * invl0;
                    float p10 = __expf(s10 - m1) * invl1;
                    float p11 = __expf(s11 - m1) * invl1;
                    p00 = (p00 > 0.01f || ((wa >> (bp + 0)) & 1u)) ? p00 : 0.f;
                    p01 = (p01 > 0.01f || ((wa >> (bp + 1)) & 1u)) ? p01 : 0.f;
                    p10 = (p10 > 0.01f || ((wb >> (bp + 0)) & 1u)) ? p10 : 0.f;
                    p11 = (p11 > 0.01f || ((wb >> (bp + 1)) & 1u)) ? p11 : 0.f;
                    __half h0, o0, h1, o1, h2v, o2, h3, o3;
                    split2(p00, h0, o0); split2(p01, h1, o1);
                    split2(p10, h2v, o2); split2(p11, h3, o3);
                    afh[2 * h2]     = pk(h0, h1);
                    afh[2 * h2 + 1] = pk(h2v, h3);
                    afl[2 * h2]     = pk(o0, o1);
                    afl[2 * h2 + 1] = pk(o2, o3);
                }
#pragma unroll
                for (int np = 0; np < 4; np++) {
                    uint32_t VH[4], VL[4];
                    ldm_x4(VH, vvh + np * 2304 + ks * 32);
                    ldm_x4(VL, vvh + 9216 + np * 2304 + ks * 32);
                    mma16816(acc2[2 * np],     afh, &VH[0]);
                    mma16816(acc2[2 * np],     afh, &VL[0]);
                    mma16816(acc2[2 * np],     afl, &VH[0]);
                    mma16816(acc2[2 * np + 1], afh, &VH[2]);
                    mma16816(acc2[2 * np + 1], afh, &VL[2]);
                    mma16816(acc2[2 * np + 1], afl, &VH[2]);
                }
            }
        }

        // epilogue: split output, write g_aoh/g_aol directly
        const int b = blockIdx.z, h = blockIdx.y;
#pragma unroll
        for (int ni = 0; ni < 8; ni++) {
            int d = ni * 8 + j2;
            __half h0, o0, h1, o1;
            split2(acc2[ni][0], h0, o0);
            split2(acc2[ni][1], h1, o1);
            size_t o = ((size_t)(b * TT + tg0) * CC + h * 64 + d) >> 1;
            ((uint32_t*)g_aoh)[o] = pk(h0, h1);
            ((uint32_t*)g_aol)[o] = pk(o0, o1);
            split2(acc2[ni][2], h0, o0);
            split2(acc2[ni][3], h1, o1);
            o = ((size_t)(b * TT + tg1) * CC + h * 64 + d) >> 1;
            ((uint32_t*)g_aoh)[o] = pk(h0, h1);
            ((uint32_t*)g_aol)[o] = pk(o0, o1);
        }
        __syncthreads();
    }
}

// ---------------------------------------------------------------------------
extern "C" void kernel_launch(void* const* d_in, const int* in_sizes, int n_in,
                              void* d_out, int out_size) {
    const float* x    = (const float*)d_in[0];
    const float* Wqkv = (const float*)d_in[1];
    const float* bqkv = (const float*)d_in[2];
    const float* Wout = (const float*)d_in[3];
    const float* bout = (const float*)d_in[4];
    float* out = (float*)d_out;

    cudaFuncSetAttribute(attn_kernel,
                         cudaFuncAttributeMaxDynamicSharedMemorySize, ATTN_SMEM);
    cudaFuncSetAttribute(hmma_gemm,
                         cudaFuncAttributeMaxDynamicSharedMemorySize, GEMM_SMEM);

    // 0) Regrow bitmask (input-independent, standalone)
    mask_kernel<<<dim3(4, TT, BB * HH), 256>>>();

    // 1) Split-f16 conversions
    conv_rows<<<(BB * TT * CC / 4 + 255) / 256, 256>>>(x, BB * TT * CC / 4);
    conv_tr<<<dim3(3 * CC / 32, CC / 32), dim3(32, 8)>>>(Wqkv, CC, 3 * CC, 0);
    conv_tr<<<dim3(CC / 32, CC / 32), dim3(32, 8)>>>(Wout, CC, CC, 1);

    // 2) QKV projection -> q,k (2-way f16), v (fp32)
    hmma_gemm<<<dim3(3 * CC / 128, BB * TT / 128), 256, GEMM_SMEM>>>(
        bqkv, nullptr, 0);

    // 2b) V -> V^T f16 hi/lo
    vt_split<<<dim3(DD / 32, TT / 32, BB * HH), dim3(32, 8)>>>();

    // 3) Attention (recompute-QK, register-P AV)
    attn_kernel<<<dim3(TT / 256, HH, BB), 256, ATTN_SMEM>>>();

    // 4) Output projection
    hmma_gemm<<<dim3(CC / 128, BB * TT / 128), 256, GEMM_SMEM>>>(
        bout, out, 1);
}